// round 1
// baseline (speedup 1.0000x reference)
#include <cuda_runtime.h>
#include <math.h>

#define BB 256
#define SS 256
#define DD 256
#define HH 4
#define DHH 64
#define LL 2
#define MM (BB*SS)          // 65536
#define FF (4*DD)           // 1024

// ---------------- scratch (no malloc allowed) ----------------
__device__ float g_x  [ (size_t)MM*DD ];
__device__ float g_q  [ (size_t)MM*DD ];
__device__ float g_k  [ (size_t)MM*DD ];
__device__ float g_v  [ (size_t)MM*DD ];
__device__ float g_ctx[ (size_t)MM*DD ];
__device__ float g_tmp[ (size_t)MM*DD ];
__device__ float g_h  [ (size_t)MM*DD ];
__device__ float g_mid[ (size_t)MM*FF ];
__device__ float g_sc [ (size_t)BB*HH*SS*SS ];

// ---------------- block reduction helper ----------------
__device__ __forceinline__ float block_sum_256(float v, float* sh) {
    int tid = threadIdx.x;
    sh[tid] = v; __syncthreads();
    #pragma unroll
    for (int s = 128; s > 0; s >>= 1) {
        if (tid < s) sh[tid] += sh[tid + s];
        __syncthreads();
    }
    float r = sh[0];
    __syncthreads();
    return r;
}

// ---------------- embedding + LN (also initializes total=out) ----------------
__global__ void embed_ln_kernel(const int* __restrict__ ids,
                                const float* __restrict__ item_emb,
                                const float* __restrict__ pos_emb,
                                float* __restrict__ x, float* __restrict__ out) {
    __shared__ float sh[256];
    int row = blockIdx.x;          // b*S + s
    int s   = row & (SS - 1);
    int tid = threadIdx.x;
    int id  = ids[row];
    float v = item_emb[(size_t)id * DD + tid] + pos_emb[s * DD + tid];
    float mu  = block_sum_256(v, sh) * (1.0f / DD);
    float d   = v - mu;
    float var = block_sum_256(d * d, sh) * (1.0f / DD);
    float o   = d * rsqrtf(var + 1e-5f);
    size_t idx = (size_t)row * DD + tid;
    x[idx] = o;
    out[idx] = o;
}

// ---------------- LN: h = LN(in) ----------------
__global__ void ln_kernel(const float* __restrict__ in, float* __restrict__ outp) {
    __shared__ float sh[256];
    int row = blockIdx.x, tid = threadIdx.x;
    size_t idx = (size_t)row * DD + tid;
    float v = in[idx];
    float mu  = block_sum_256(v, sh) * (1.0f / DD);
    float d   = v - mu;
    float var = block_sum_256(d * d, sh) * (1.0f / DD);
    outp[idx] = d * rsqrtf(var + 1e-5f);
}

// ---------------- LN + accumulate: x = LN(in); total += x ----------------
__global__ void ln_accum_kernel(const float* __restrict__ in, float* __restrict__ x,
                                float* __restrict__ total) {
    __shared__ float sh[256];
    int row = blockIdx.x, tid = threadIdx.x;
    size_t idx = (size_t)row * DD + tid;
    float v = in[idx];
    float mu  = block_sum_256(v, sh) * (1.0f / DD);
    float d   = v - mu;
    float var = block_sum_256(d * d, sh) * (1.0f / DD);
    float o = d * rsqrtf(var + 1e-5f);
    x[idx] = o;
    total[idx] += o;
}

// ---------------- generic GEMM: C[M,N] = A[M,K] @ W[K,N] + bias (+epilogue) ----------
// EPI: 0 = bias, 1 = bias + exact GELU, 2 = bias + residual add
template<int EPI>
__global__ void gemm_bias_kernel(const float* __restrict__ A, const float* __restrict__ W,
                                 const float* __restrict__ bias,
                                 const float* __restrict__ resid,
                                 float* __restrict__ C, int M, int N, int K) {
    __shared__ float As[16][68];
    __shared__ float Ws[16][64];
    const int tid = threadIdx.x;
    const int tx = tid & 15, ty = tid >> 4;
    const int bm = blockIdx.y << 6, bn = blockIdx.x << 6;
    const int arow = tid >> 2, acol = (tid & 3) << 2;
    const int wrow = tid >> 4, wcol = (tid & 15) << 2;
    float acc[4][4] = {};
    for (int k0 = 0; k0 < K; k0 += 16) {
        float4 av = *(const float4*)(A + (size_t)(bm + arow) * K + k0 + acol);
        As[acol + 0][arow] = av.x; As[acol + 1][arow] = av.y;
        As[acol + 2][arow] = av.z; As[acol + 3][arow] = av.w;
        *(float4*)(&Ws[wrow][wcol]) = *(const float4*)(W + (size_t)(k0 + wrow) * N + bn + wcol);
        __syncthreads();
        #pragma unroll
        for (int kk = 0; kk < 16; kk++) {
            float4 a = *(const float4*)(&As[kk][ty << 2]);
            float4 b = *(const float4*)(&Ws[kk][tx << 2]);
            acc[0][0] += a.x * b.x; acc[0][1] += a.x * b.y; acc[0][2] += a.x * b.z; acc[0][3] += a.x * b.w;
            acc[1][0] += a.y * b.x; acc[1][1] += a.y * b.y; acc[1][2] += a.y * b.z; acc[1][3] += a.y * b.w;
            acc[2][0] += a.z * b.x; acc[2][1] += a.z * b.y; acc[2][2] += a.z * b.z; acc[2][3] += a.z * b.w;
            acc[3][0] += a.w * b.x; acc[3][1] += a.w * b.y; acc[3][2] += a.w * b.z; acc[3][3] += a.w * b.w;
        }
        __syncthreads();
    }
    #pragma unroll
    for (int i = 0; i < 4; i++) {
        int row = bm + (ty << 2) + i;
        int colbase = bn + (tx << 2);
        float4 cv;
        float* cp = &cv.x;
        #pragma unroll
        for (int j = 0; j < 4; j++) {
            float c = acc[i][j] + bias[colbase + j];
            if (EPI == 1) c = 0.5f * c * (1.0f + erff(c * 0.7071067811865476f));
            if (EPI == 2) c += resid[(size_t)row * N + colbase + j];
            cp[j] = c;
        }
        *(float4*)(C + (size_t)row * N + colbase) = cv;
    }
}

// ---------------- attention scores: sc[b,h,q,k] = scale*q.k + mask bias ----------------
__global__ void attn_scores_kernel(const float* __restrict__ q, const float* __restrict__ k,
                                   const int* __restrict__ ids, float* __restrict__ sc) {
    __shared__ float Qs[16][68];
    __shared__ float Ks[16][68];
    const int bh = blockIdx.z, b = bh >> 2, h = bh & 3;
    const float* A  = q + (size_t)b * SS * DD + h * DHH;
    const float* Bm = k + (size_t)b * SS * DD + h * DHH;
    const int m0 = blockIdx.y << 6, n0 = blockIdx.x << 6;
    const int tid = threadIdx.x;
    const int tx = tid & 15, ty = tid >> 4;
    const int lrow = tid >> 2, lcol = (tid & 3) << 2;
    float acc[4][4] = {};
    for (int k0 = 0; k0 < DHH; k0 += 16) {
        float4 av = *(const float4*)(A + (size_t)(m0 + lrow) * DD + k0 + lcol);
        Qs[lcol + 0][lrow] = av.x; Qs[lcol + 1][lrow] = av.y;
        Qs[lcol + 2][lrow] = av.z; Qs[lcol + 3][lrow] = av.w;
        float4 bv = *(const float4*)(Bm + (size_t)(n0 + lrow) * DD + k0 + lcol);
        Ks[lcol + 0][lrow] = bv.x; Ks[lcol + 1][lrow] = bv.y;
        Ks[lcol + 2][lrow] = bv.z; Ks[lcol + 3][lrow] = bv.w;
        __syncthreads();
        #pragma unroll
        for (int kk = 0; kk < 16; kk++) {
            float4 a = *(const float4*)(&Qs[kk][ty << 2]);
            float4 bq = *(const float4*)(&Ks[kk][tx << 2]);
            acc[0][0] += a.x * bq.x; acc[0][1] += a.x * bq.y; acc[0][2] += a.x * bq.z; acc[0][3] += a.x * bq.w;
            acc[1][0] += a.y * bq.x; acc[1][1] += a.y * bq.y; acc[1][2] += a.y * bq.z; acc[1][3] += a.y * bq.w;
            acc[2][0] += a.z * bq.x; acc[2][1] += a.z * bq.y; acc[2][2] += a.z * bq.z; acc[2][3] += a.z * bq.w;
            acc[3][0] += a.w * bq.x; acc[3][1] += a.w * bq.y; acc[3][2] += a.w * bq.z; acc[3][3] += a.w * bq.w;
        }
        __syncthreads();
    }
    const float scale = 0.125f;   // 1/sqrt(64)
    const int* idb = ids + b * SS;
    float* Cp = sc + (size_t)bh * SS * SS;
    #pragma unroll
    for (int i = 0; i < 4; i++) {
        int row = m0 + (ty << 2) + i;
        int colbase = n0 + (tx << 2);
        float4 cv; float* cp = &cv.x;
        #pragma unroll
        for (int j = 0; j < 4; j++) {
            int col = colbase + j;
            float biasv = (idb[col] > 0 && col <= row) ? 0.0f : -10000.0f;
            cp[j] = acc[i][j] * scale + biasv;
        }
        *(float4*)(Cp + (size_t)row * SS + colbase) = cv;
    }
}

// ---------------- row softmax over 256 ----------------
__global__ void softmax_kernel(float* __restrict__ sc) {
    __shared__ float sh[256];
    size_t row = blockIdx.x;
    float* p = sc + row * SS;
    int tid = threadIdx.x;
    float v = p[tid];
    sh[tid] = v; __syncthreads();
    #pragma unroll
    for (int s = 128; s > 0; s >>= 1) {
        if (tid < s) sh[tid] = fmaxf(sh[tid], sh[tid + s]);
        __syncthreads();
    }
    float m = sh[0]; __syncthreads();
    float e = __expf(v - m);
    sh[tid] = e; __syncthreads();
    #pragma unroll
    for (int s = 128; s > 0; s >>= 1) {
        if (tid < s) sh[tid] += sh[tid + s];
        __syncthreads();
    }
    p[tid] = e / sh[0];
}

// ---------------- PV: ctx[b,:,h*64:(h+1)*64] = probs @ v ----------------
__global__ void attn_pv_kernel(const float* __restrict__ sc, const float* __restrict__ v,
                               float* __restrict__ ctx) {
    __shared__ float As[16][68];
    __shared__ float Bs[16][64];
    const int bh = blockIdx.z, b = bh >> 2, h = bh & 3;
    const float* A  = sc + (size_t)bh * SS * SS;
    const float* Bm = v  + (size_t)b * SS * DD + h * DHH;
    float* Cp       = ctx + (size_t)b * SS * DD + h * DHH;
    const int m0 = blockIdx.y << 6;
    const int tid = threadIdx.x;
    const int tx = tid & 15, ty = tid >> 4;
    const int arow = tid >> 2, acol = (tid & 3) << 2;
    const int wrow = tid >> 4, wcol = (tid & 15) << 2;
    float acc[4][4] = {};
    for (int k0 = 0; k0 < SS; k0 += 16) {
        float4 av = *(const float4*)(A + (size_t)(m0 + arow) * SS + k0 + acol);
        As[acol + 0][arow] = av.x; As[acol + 1][arow] = av.y;
        As[acol + 2][arow] = av.z; As[acol + 3][arow] = av.w;
        *(float4*)(&Bs[wrow][wcol]) = *(const float4*)(Bm + (size_t)(k0 + wrow) * DD + wcol);
        __syncthreads();
        #pragma unroll
        for (int kk = 0; kk < 16; kk++) {
            float4 a = *(const float4*)(&As[kk][ty << 2]);
            float4 bq = *(const float4*)(&Bs[kk][tx << 2]);
            acc[0][0] += a.x * bq.x; acc[0][1] += a.x * bq.y; acc[0][2] += a.x * bq.z; acc[0][3] += a.x * bq.w;
            acc[1][0] += a.y * bq.x; acc[1][1] += a.y * bq.y; acc[1][2] += a.y * bq.z; acc[1][3] += a.y * bq.w;
            acc[2][0] += a.z * bq.x; acc[2][1] += a.z * bq.y; acc[2][2] += a.z * bq.z; acc[2][3] += a.z * bq.w;
            acc[3][0] += a.w * bq.x; acc[3][1] += a.w * bq.y; acc[3][2] += a.w * bq.z; acc[3][3] += a.w * bq.w;
        }
        __syncthreads();
    }
    #pragma unroll
    for (int i = 0; i < 4; i++) {
        int row = m0 + (ty << 2) + i;
        int colbase = tx << 2;
        float4 cv; float* cp = &cv.x;
        #pragma unroll
        for (int j = 0; j < 4; j++) cp[j] = acc[i][j];
        *(float4*)(Cp + (size_t)row * DD + colbase) = cv;
    }
}

// ---------------- host orchestration ----------------
extern "C" void kernel_launch(void* const* d_in, const int* in_sizes, int n_in,
                              void* d_out, int out_size) {
    const int*   ids      = (const int*)  d_in[0];
    const float* item_emb = (const float*)d_in[1];
    const float* pos_emb  = (const float*)d_in[2];
    const float* Wq = (const float*)d_in[3];
    const float* bq = (const float*)d_in[4];
    const float* Wk = (const float*)d_in[5];
    const float* bk = (const float*)d_in[6];
    const float* Wv = (const float*)d_in[7];
    const float* bv = (const float*)d_in[8];
    const float* Wo = (const float*)d_in[9];
    const float* bo = (const float*)d_in[10];
    const float* W1 = (const float*)d_in[11];
    const float* b1 = (const float*)d_in[12];
    const float* W2 = (const float*)d_in[13];
    const float* b2 = (const float*)d_in[14];
    float* out = (float*)d_out;

    float *x, *q, *k, *v, *ctx, *tmp, *h, *mid, *sc;
    cudaGetSymbolAddress((void**)&x,   g_x);
    cudaGetSymbolAddress((void**)&q,   g_q);
    cudaGetSymbolAddress((void**)&k,   g_k);
    cudaGetSymbolAddress((void**)&v,   g_v);
    cudaGetSymbolAddress((void**)&ctx, g_ctx);
    cudaGetSymbolAddress((void**)&tmp, g_tmp);
    cudaGetSymbolAddress((void**)&h,   g_h);
    cudaGetSymbolAddress((void**)&mid, g_mid);
    cudaGetSymbolAddress((void**)&sc,  g_sc);

    embed_ln_kernel<<<MM, 256>>>(ids, item_emb, pos_emb, x, out);

    dim3 gProj(DD / 64, MM / 64);       // (4, 1024)
    dim3 gFF1(FF / 64, MM / 64);        // (16, 1024)
    dim3 gSc(SS / 64, SS / 64, BB * HH);// (4, 4, 1024)
    dim3 gPv(1, SS / 64, BB * HH);      // (1, 4, 1024)

    for (int l = 0; l < LL; l++) {
        const float* Wql = Wq + (size_t)l * DD * DD; const float* bql = bq + l * DD;
        const float* Wkl = Wk + (size_t)l * DD * DD; const float* bkl = bk + l * DD;
        const float* Wvl = Wv + (size_t)l * DD * DD; const float* bvl = bv + l * DD;
        const float* Wol = Wo + (size_t)l * DD * DD; const float* bol = bo + l * DD;
        const float* W1l = W1 + (size_t)l * DD * FF; const float* b1l = b1 + l * FF;
        const float* W2l = W2 + (size_t)l * FF * DD; const float* b2l = b2 + l * DD;

        gemm_bias_kernel<0><<<gProj, 256>>>(x, Wql, bql, nullptr, q, MM, DD, DD);
        gemm_bias_kernel<0><<<gProj, 256>>>(x, Wkl, bkl, nullptr, k, MM, DD, DD);
        gemm_bias_kernel<0><<<gProj, 256>>>(x, Wvl, bvl, nullptr, v, MM, DD, DD);

        attn_scores_kernel<<<gSc, 256>>>(q, k, ids, sc);
        softmax_kernel<<<(unsigned)(BB * HH * SS), 256>>>(sc);
        attn_pv_kernel<<<gPv, 256>>>(sc, v, ctx);

        gemm_bias_kernel<2><<<gProj, 256>>>(ctx, Wol, bol, x, tmp, MM, DD, DD);
        ln_kernel<<<MM, 256>>>(tmp, h);

        gemm_bias_kernel<1><<<gFF1, 256>>>(h, W1l, b1l, nullptr, mid, MM, FF, DD);
        gemm_bias_kernel<0><<<gProj, 256>>>(mid, W2l, b2l, nullptr, tmp, MM, DD, FF);
        ln_accum_kernel<<<MM, 256>>>(tmp, x, out);
    }
}

// round 2
// speedup vs baseline: 2.0550x; 2.0550x over previous
#include <cuda_runtime.h>
#include <math.h>
#include <stdint.h>

#define BB 256
#define SS 256
#define DD 256
#define HH 4
#define DHH 64
#define LL 2
#define MM (BB*SS)          // 65536
#define FF (4*DD)           // 1024

// ---------------- scratch (no malloc allowed) ----------------
__device__ float g_x  [ (size_t)MM*DD ];
__device__ float g_q  [ (size_t)MM*DD ];
__device__ float g_k  [ (size_t)MM*DD ];
__device__ float g_v  [ (size_t)MM*DD ];
__device__ float g_ctx[ (size_t)MM*DD ];
__device__ float g_tmp[ (size_t)MM*DD ];
__device__ float g_h  [ (size_t)MM*DD ];
__device__ float g_mid[ (size_t)MM*FF ];
__device__ float g_sc [ (size_t)BB*HH*SS*SS ];

// ---------------- helpers ----------------
__device__ __forceinline__ float block_sum_256(float v, float* sh) {
    int tid = threadIdx.x;
    sh[tid] = v; __syncthreads();
    #pragma unroll
    for (int s = 128; s > 0; s >>= 1) {
        if (tid < s) sh[tid] += sh[tid + s];
        __syncthreads();
    }
    float r = sh[0];
    __syncthreads();
    return r;
}

__device__ __forceinline__ float to_tf32(float x) {
    float r;
    asm("cvt.rna.tf32.f32 %0, %1;" : "=f"(r) : "f"(x));
    return r;
}

__device__ __forceinline__ void mma_tf32(float* d, const uint32_t* a, const uint32_t* b) {
    asm volatile("mma.sync.aligned.m16n8k8.row.col.f32.tf32.tf32.f32 "
        "{%0,%1,%2,%3}, {%4,%5,%6,%7}, {%8,%9}, {%0,%1,%2,%3};"
        : "+f"(d[0]), "+f"(d[1]), "+f"(d[2]), "+f"(d[3])
        : "r"(a[0]), "r"(a[1]), "r"(a[2]), "r"(a[3]), "r"(b[0]), "r"(b[1]));
}

// ---------------- embedding + LN (also initializes total=out) ----------------
__global__ void embed_ln_kernel(const int* __restrict__ ids,
                                const float* __restrict__ item_emb,
                                const float* __restrict__ pos_emb,
                                float* __restrict__ x, float* __restrict__ out) {
    __shared__ float sh[256];
    int row = blockIdx.x;
    int s   = row & (SS - 1);
    int tid = threadIdx.x;
    int id  = ids[row];
    float v = item_emb[(size_t)id * DD + tid] + pos_emb[s * DD + tid];
    float mu  = block_sum_256(v, sh) * (1.0f / DD);
    float d   = v - mu;
    float var = block_sum_256(d * d, sh) * (1.0f / DD);
    float o   = d * rsqrtf(var + 1e-5f);
    size_t idx = (size_t)row * DD + tid;
    x[idx] = o;
    out[idx] = o;
}

__global__ void ln_kernel(const float* __restrict__ in, float* __restrict__ outp) {
    __shared__ float sh[256];
    int row = blockIdx.x, tid = threadIdx.x;
    size_t idx = (size_t)row * DD + tid;
    float v = in[idx];
    float mu  = block_sum_256(v, sh) * (1.0f / DD);
    float d   = v - mu;
    float var = block_sum_256(d * d, sh) * (1.0f / DD);
    outp[idx] = d * rsqrtf(var + 1e-5f);
}

__global__ void ln_accum_kernel(const float* __restrict__ in, float* __restrict__ x,
                                float* __restrict__ total) {
    __shared__ float sh[256];
    int row = blockIdx.x, tid = threadIdx.x;
    size_t idx = (size_t)row * DD + tid;
    float v = in[idx];
    float mu  = block_sum_256(v, sh) * (1.0f / DD);
    float d   = v - mu;
    float var = block_sum_256(d * d, sh) * (1.0f / DD);
    float o = d * rsqrtf(var + 1e-5f);
    x[idx] = o;
    total[idx] += o;
}

// ---------------- row softmax over 256 ----------------
__global__ void softmax_kernel(float* __restrict__ sc) {
    __shared__ float sh[256];
    size_t row = blockIdx.x;
    float* p = sc + row * SS;
    int tid = threadIdx.x;
    float v = p[tid];
    sh[tid] = v; __syncthreads();
    #pragma unroll
    for (int s = 128; s > 0; s >>= 1) {
        if (tid < s) sh[tid] = fmaxf(sh[tid], sh[tid + s]);
        __syncthreads();
    }
    float m = sh[0]; __syncthreads();
    float e = __expf(v - m);
    sh[tid] = e; __syncthreads();
    #pragma unroll
    for (int s = 128; s > 0; s >>= 1) {
        if (tid < s) sh[tid] += sh[tid + s];
        __syncthreads();
    }
    p[tid] = e / sh[0];
}

// =====================================================================
// TF32 tensor-core GEMM.
//   C[M,N] = A[M,K] @ B + epilogue
//   BTRANS==0: B is [K,N] row-major (ldb = row stride)
//   BTRANS==1: B is [N,K] row-major (k contiguous; used for Q.K^T)
// EPI: 0=bias  1=bias+GELU(exact)  2=bias+resid  3=scores(scale+mask)  4=none(PV)
// Block tile: 128 x BN, BK=16.  Warp tile 64x32.
// =====================================================================
template<int EPI, int BN, int BTRANS>
__global__ void __launch_bounds__((BN==128) ? 256 : 128)
mma_gemm_kernel(const float* __restrict__ A, const float* __restrict__ Bm,
                const float* __restrict__ bias, const float* __restrict__ resid,
                float* __restrict__ C, const int* __restrict__ ids,
                int M, int N, int K, int lda, int ldb, int ldc)
{
    constexpr int BM = 128;
    constexpr int NTHREADS = (BN == 128) ? 256 : 128;
    constexpr int AROWS = NTHREADS / 4;        // rows of A loaded per iter
    constexpr int A_ITERS = BM / AROWS;        // 2 (256t) or 4 (128t)
    constexpr int BSTRIDE = BTRANS ? 20 : (BN + 8);

    __shared__ float As[BM * 20];
    __shared__ float Bs[BTRANS ? (BN * 20) : (16 * (BN + 8))];

    const int tid  = threadIdx.x;
    const int lane = tid & 31;
    const int wid  = tid >> 5;
    const int warp_m = wid & 1;       // 0..1
    const int warp_n = wid >> 1;      // 0..3 (BN=128) or 0..1 (BN=64)
    const int r = lane >> 2;          // groupID 0..7
    const int cfour = lane & 3;       // tid-in-group 0..3

    const int bm = blockIdx.y * BM;
    const int bn = blockIdx.x * BN;

    if (EPI == 3) {
        int bh = blockIdx.z, b = bh >> 2, h = bh & 3;
        A   += (size_t)b * SS * DD + h * DHH;
        Bm  += (size_t)b * SS * DD + h * DHH;
        C   += (size_t)bh * SS * SS;
        ids += b * SS;
    }
    if (EPI == 4) {
        int bh = blockIdx.z, b = bh >> 2, h = bh & 3;
        A  += (size_t)bh * SS * SS;
        Bm += (size_t)b * SS * DD + h * DHH;
        C  += (size_t)b * SS * DD + h * DHH;
    }

    // -------- global load index setup --------
    const int arow0 = tid >> 2;                // A (and BTRANS-B) row within tile
    const int acol  = (tid & 3) << 2;          // 0,4,8,12
    // BTRANS==0 B loader: 16 x BN floats, float4-granular
    constexpr int BCOL4 = BN / 4;
    const int bidx0 = tid;                     // + i*NTHREADS

    float4 aReg[A_ITERS];
    float4 bReg[2];   // both layouts load 2 float4 per thread (BTRANS1 only uses layout below)
    float4 btReg[2];  // BTRANS==1 loader regs (2 iters of A-style rows)

    // ---- load tile s=0 directly into smem ----
    {
        #pragma unroll
        for (int i = 0; i < A_ITERS; i++) {
            float4 av = *(const float4*)(A + (size_t)(bm + arow0 + i * AROWS) * lda + acol);
            float* dst = &As[(arow0 + i * AROWS) * 20 + acol];
            dst[0] = to_tf32(av.x); dst[1] = to_tf32(av.y);
            dst[2] = to_tf32(av.z); dst[3] = to_tf32(av.w);
        }
        if (BTRANS) {
            #pragma unroll
            for (int i = 0; i < 2; i++) {
                int row = arow0 + i * AROWS;
                if (row < BN) {
                    float4 bv = *(const float4*)(Bm + (size_t)(bn + row) * ldb + acol);
                    float* dst = &Bs[row * 20 + acol];
                    dst[0] = to_tf32(bv.x); dst[1] = to_tf32(bv.y);
                    dst[2] = to_tf32(bv.z); dst[3] = to_tf32(bv.w);
                }
            }
        } else {
            #pragma unroll
            for (int i = 0; i < 2; i++) {
                int idx = bidx0 + i * NTHREADS;
                int brow = idx / BCOL4, bc4 = idx % BCOL4;
                float4 bv = *(const float4*)(Bm + (size_t)brow * ldb + bn + bc4 * 4);
                float* dst = &Bs[brow * (BN + 8) + bc4 * 4];
                dst[0] = to_tf32(bv.x); dst[1] = to_tf32(bv.y);
                dst[2] = to_tf32(bv.z); dst[3] = to_tf32(bv.w);
            }
        }
    }
    __syncthreads();

    float acc[4][4][4];
    #pragma unroll
    for (int i = 0; i < 4; i++)
        #pragma unroll
        for (int j = 0; j < 4; j++)
            #pragma unroll
            for (int p = 0; p < 4; p++) acc[i][j][p] = 0.0f;

    const int nsteps = K >> 4;
    for (int s = 0; s < nsteps; s++) {
        const bool has_next = (s + 1) < nsteps;
        const int knext = (s + 1) << 4;
        if (has_next) {
            #pragma unroll
            for (int i = 0; i < A_ITERS; i++)
                aReg[i] = *(const float4*)(A + (size_t)(bm + arow0 + i * AROWS) * lda + knext + acol);
            if (BTRANS) {
                #pragma unroll
                for (int i = 0; i < 2; i++) {
                    int row = arow0 + i * AROWS;
                    if (row < BN)
                        btReg[i] = *(const float4*)(Bm + (size_t)(bn + row) * ldb + knext + acol);
                }
            } else {
                #pragma unroll
                for (int i = 0; i < 2; i++) {
                    int idx = bidx0 + i * NTHREADS;
                    int brow = idx / BCOL4, bc4 = idx % BCOL4;
                    bReg[i] = *(const float4*)(Bm + (size_t)(knext + brow) * ldb + bn + bc4 * 4);
                }
            }
        }

        // -------- compute: two k=8 sub-steps --------
        #pragma unroll
        for (int k8 = 0; k8 < 2; k8++) {
            const int kc = k8 * 8 + cfour;
            uint32_t afr[4][4];
            #pragma unroll
            for (int i = 0; i < 4; i++) {
                int m = warp_m * 64 + i * 16;
                afr[i][0] = __float_as_uint(As[(m + r) * 20 + kc]);
                afr[i][1] = __float_as_uint(As[(m + 8 + r) * 20 + kc]);
                afr[i][2] = __float_as_uint(As[(m + r) * 20 + kc + 4]);
                afr[i][3] = __float_as_uint(As[(m + 8 + r) * 20 + kc + 4]);
            }
            uint32_t bfr[4][2];
            #pragma unroll
            for (int j = 0; j < 4; j++) {
                int n = warp_n * 32 + j * 8 + r;
                if (BTRANS) {
                    bfr[j][0] = __float_as_uint(Bs[n * 20 + kc]);
                    bfr[j][1] = __float_as_uint(Bs[n * 20 + kc + 4]);
                } else {
                    bfr[j][0] = __float_as_uint(Bs[kc * (BN + 8) + n]);
                    bfr[j][1] = __float_as_uint(Bs[(kc + 4) * (BN + 8) + n]);
                }
            }
            #pragma unroll
            for (int i = 0; i < 4; i++)
                #pragma unroll
                for (int j = 0; j < 4; j++)
                    mma_tf32(acc[i][j], afr[i], bfr[j]);
        }

        if (has_next) {
            __syncthreads();
            #pragma unroll
            for (int i = 0; i < A_ITERS; i++) {
                float* dst = &As[(arow0 + i * AROWS) * 20 + acol];
                dst[0] = to_tf32(aReg[i].x); dst[1] = to_tf32(aReg[i].y);
                dst[2] = to_tf32(aReg[i].z); dst[3] = to_tf32(aReg[i].w);
            }
            if (BTRANS) {
                #pragma unroll
                for (int i = 0; i < 2; i++) {
                    int row = arow0 + i * AROWS;
                    if (row < BN) {
                        float* dst = &Bs[row * 20 + acol];
                        dst[0] = to_tf32(btReg[i].x); dst[1] = to_tf32(btReg[i].y);
                        dst[2] = to_tf32(btReg[i].z); dst[3] = to_tf32(btReg[i].w);
                    }
                }
            } else {
                #pragma unroll
                for (int i = 0; i < 2; i++) {
                    int idx = bidx0 + i * NTHREADS;
                    int brow = idx / BCOL4, bc4 = idx % BCOL4;
                    float* dst = &Bs[brow * (BN + 8) + bc4 * 4];
                    dst[0] = to_tf32(bReg[i].x); dst[1] = to_tf32(bReg[i].y);
                    dst[2] = to_tf32(bReg[i].z); dst[3] = to_tf32(bReg[i].w);
                }
            }
            __syncthreads();
        }
    }

    // -------- epilogue + store --------
    #pragma unroll
    for (int i = 0; i < 4; i++) {
        #pragma unroll
        for (int j = 0; j < 4; j++) {
            int gr0 = bm + warp_m * 64 + i * 16 + r;
            int gc  = bn + warp_n * 32 + j * 8 + cfour * 2;
            float v00 = acc[i][j][0], v01 = acc[i][j][1];
            float v10 = acc[i][j][2], v11 = acc[i][j][3];
            if (EPI == 0 || EPI == 1 || EPI == 2) {
                float b0 = bias[gc], b1 = bias[gc + 1];
                v00 += b0; v01 += b1; v10 += b0; v11 += b1;
            }
            if (EPI == 1) {
                v00 = 0.5f * v00 * (1.0f + erff(v00 * 0.7071067811865476f));
                v01 = 0.5f * v01 * (1.0f + erff(v01 * 0.7071067811865476f));
                v10 = 0.5f * v10 * (1.0f + erff(v10 * 0.7071067811865476f));
                v11 = 0.5f * v11 * (1.0f + erff(v11 * 0.7071067811865476f));
            }
            if (EPI == 2) {
                v00 += resid[(size_t)gr0 * ldc + gc];
                v01 += resid[(size_t)gr0 * ldc + gc + 1];
                v10 += resid[(size_t)(gr0 + 8) * ldc + gc];
                v11 += resid[(size_t)(gr0 + 8) * ldc + gc + 1];
            }
            if (EPI == 3) {
                bool ok0 = (ids[gc] > 0), ok1 = (ids[gc + 1] > 0);
                v00 = v00 * 0.125f + ((ok0 && gc     <= gr0    ) ? 0.0f : -10000.0f);
                v01 = v01 * 0.125f + ((ok1 && gc + 1 <= gr0    ) ? 0.0f : -10000.0f);
                v10 = v10 * 0.125f + ((ok0 && gc     <= gr0 + 8) ? 0.0f : -10000.0f);
                v11 = v11 * 0.125f + ((ok1 && gc + 1 <= gr0 + 8) ? 0.0f : -10000.0f);
            }
            *(float2*)(C + (size_t)gr0 * ldc + gc)       = make_float2(v00, v01);
            *(float2*)(C + (size_t)(gr0 + 8) * ldc + gc) = make_float2(v10, v11);
        }
    }
}

// ---------------- host orchestration ----------------
extern "C" void kernel_launch(void* const* d_in, const int* in_sizes, int n_in,
                              void* d_out, int out_size) {
    const int*   ids      = (const int*)  d_in[0];
    const float* item_emb = (const float*)d_in[1];
    const float* pos_emb  = (const float*)d_in[2];
    const float* Wq = (const float*)d_in[3];
    const float* bq = (const float*)d_in[4];
    const float* Wk = (const float*)d_in[5];
    const float* bk = (const float*)d_in[6];
    const float* Wv = (const float*)d_in[7];
    const float* bv = (const float*)d_in[8];
    const float* Wo = (const float*)d_in[9];
    const float* bo = (const float*)d_in[10];
    const float* W1 = (const float*)d_in[11];
    const float* b1 = (const float*)d_in[12];
    const float* W2 = (const float*)d_in[13];
    const float* b2 = (const float*)d_in[14];
    float* out = (float*)d_out;

    float *x, *q, *k, *v, *ctx, *tmp, *h, *mid, *sc;
    cudaGetSymbolAddress((void**)&x,   g_x);
    cudaGetSymbolAddress((void**)&q,   g_q);
    cudaGetSymbolAddress((void**)&k,   g_k);
    cudaGetSymbolAddress((void**)&v,   g_v);
    cudaGetSymbolAddress((void**)&ctx, g_ctx);
    cudaGetSymbolAddress((void**)&tmp, g_tmp);
    cudaGetSymbolAddress((void**)&h,   g_h);
    cudaGetSymbolAddress((void**)&mid, g_mid);
    cudaGetSymbolAddress((void**)&sc,  g_sc);

    embed_ln_kernel<<<MM, 256>>>(ids, item_emb, pos_emb, x, out);

    dim3 gProj(DD / 128, MM / 128);          // (2, 512)
    dim3 gFF1(FF / 128, MM / 128);           // (8, 512)
    dim3 gSc(SS / 128, SS / 128, BB * HH);   // (2, 2, 1024)
    dim3 gPv(1, SS / 128, BB * HH);          // (1, 2, 1024)

    for (int l = 0; l < LL; l++) {
        const float* Wql = Wq + (size_t)l * DD * DD; const float* bql = bq + l * DD;
        const float* Wkl = Wk + (size_t)l * DD * DD; const float* bkl = bk + l * DD;
        const float* Wvl = Wv + (size_t)l * DD * DD; const float* bvl = bv + l * DD;
        const float* Wol = Wo + (size_t)l * DD * DD; const float* bol = bo + l * DD;
        const float* W1l = W1 + (size_t)l * DD * FF; const float* b1l = b1 + l * FF;
        const float* W2l = W2 + (size_t)l * FF * DD; const float* b2l = b2 + l * DD;

        mma_gemm_kernel<0,128,0><<<gProj, 256>>>(x, Wql, bql, nullptr, q, nullptr, MM, DD, DD, DD, DD, DD);
        mma_gemm_kernel<0,128,0><<<gProj, 256>>>(x, Wkl, bkl, nullptr, k, nullptr, MM, DD, DD, DD, DD, DD);
        mma_gemm_kernel<0,128,0><<<gProj, 256>>>(x, Wvl, bvl, nullptr, v, nullptr, MM, DD, DD, DD, DD, DD);

        mma_gemm_kernel<3,128,1><<<gSc, 256>>>(q, k, nullptr, nullptr, sc, ids, SS, SS, DHH, DD, DD, SS);
        softmax_kernel<<<(unsigned)(BB * HH * SS), 256>>>(sc);
        mma_gemm_kernel<4,64,0><<<gPv, 128>>>(sc, v, nullptr, nullptr, ctx, nullptr, SS, DHH, SS, SS, DD, DD);

        mma_gemm_kernel<2,128,0><<<gProj, 256>>>(ctx, Wol, bol, x, tmp, nullptr, MM, DD, DD, DD, DD, DD);
        ln_kernel<<<MM, 256>>>(tmp, h);

        mma_gemm_kernel<1,128,0><<<gFF1, 256>>>(h, W1l, b1l, nullptr, mid, nullptr, MM, FF, DD, DD, FF, FF);
        mma_gemm_kernel<0,128,0><<<gProj, 256>>>(mid, W2l, b2l, nullptr, tmp, nullptr, MM, DD, FF, FF, DD, DD);
        ln_accum_kernel<<<MM, 256>>>(tmp, x, out);
    }
}

// round 3
// speedup vs baseline: 2.5031x; 1.2180x over previous
#include <cuda_runtime.h>
#include <math.h>
#include <stdint.h>

#define BB 256
#define SS 256
#define DD 256
#define HH 4
#define DHH 64
#define LL 2
#define MM (BB*SS)          // 65536
#define FF (4*DD)           // 1024

// ---------------- scratch (no malloc allowed) ----------------
__device__ float g_x  [ (size_t)MM*DD ];
__device__ float g_q  [ (size_t)MM*DD ];
__device__ float g_k  [ (size_t)MM*DD ];
__device__ float g_v  [ (size_t)MM*DD ];
__device__ float g_ctx[ (size_t)MM*DD ];
__device__ float g_tmp[ (size_t)MM*DD ];
__device__ float g_h  [ (size_t)MM*DD ];
__device__ float g_mid[ (size_t)MM*FF ];

// ---------------- helpers ----------------
__device__ __forceinline__ float block_sum_256(float v, float* sh) {
    int tid = threadIdx.x;
    sh[tid] = v; __syncthreads();
    #pragma unroll
    for (int s = 128; s > 0; s >>= 1) {
        if (tid < s) sh[tid] += sh[tid + s];
        __syncthreads();
    }
    float r = sh[0];
    __syncthreads();
    return r;
}

__device__ __forceinline__ float to_tf32(float x) {
    float r;
    asm("cvt.rna.tf32.f32 %0, %1;" : "=f"(r) : "f"(x));
    return r;
}

__device__ __forceinline__ void mma_tf32(float* d, const uint32_t* a, const uint32_t* b) {
    asm volatile("mma.sync.aligned.m16n8k8.row.col.f32.tf32.tf32.f32 "
        "{%0,%1,%2,%3}, {%4,%5,%6,%7}, {%8,%9}, {%0,%1,%2,%3};"
        : "+f"(d[0]), "+f"(d[1]), "+f"(d[2]), "+f"(d[3])
        : "r"(a[0]), "r"(a[1]), "r"(a[2]), "r"(a[3]), "r"(b[0]), "r"(b[1]));
}

__device__ __forceinline__ uint32_t f2u(float x) { return __float_as_uint(x); }

// ---------------- embedding + LN (also initializes total=out) ----------------
__global__ void embed_ln_kernel(const int* __restrict__ ids,
                                const float* __restrict__ item_emb,
                                const float* __restrict__ pos_emb,
                                float* __restrict__ x, float* __restrict__ out) {
    __shared__ float sh[256];
    int row = blockIdx.x;
    int s   = row & (SS - 1);
    int tid = threadIdx.x;
    int id  = ids[row];
    float v = item_emb[(size_t)id * DD + tid] + pos_emb[s * DD + tid];
    float mu  = block_sum_256(v, sh) * (1.0f / DD);
    float d   = v - mu;
    float var = block_sum_256(d * d, sh) * (1.0f / DD);
    float o   = d * rsqrtf(var + 1e-5f);
    size_t idx = (size_t)row * DD + tid;
    x[idx] = o;
    out[idx] = o;
}

__global__ void ln_kernel(const float* __restrict__ in, float* __restrict__ outp) {
    __shared__ float sh[256];
    int row = blockIdx.x, tid = threadIdx.x;
    size_t idx = (size_t)row * DD + tid;
    float v = in[idx];
    float mu  = block_sum_256(v, sh) * (1.0f / DD);
    float d   = v - mu;
    float var = block_sum_256(d * d, sh) * (1.0f / DD);
    outp[idx] = d * rsqrtf(var + 1e-5f);
}

__global__ void ln_accum_kernel(const float* __restrict__ in, float* __restrict__ x,
                                float* __restrict__ total) {
    __shared__ float sh[256];
    int row = blockIdx.x, tid = threadIdx.x;
    size_t idx = (size_t)row * DD + tid;
    float v = in[idx];
    float mu  = block_sum_256(v, sh) * (1.0f / DD);
    float d   = v - mu;
    float var = block_sum_256(d * d, sh) * (1.0f / DD);
    float o = d * rsqrtf(var + 1e-5f);
    x[idx] = o;
    total[idx] += o;
}

// =====================================================================
// TF32 tensor-core GEMM: C[M,N] = A[M,K] @ B[K,N] + bias (+ epilogue)
// EPI: 0=bias  1=bias+GELU(exact)  2=bias+resid
// Block tile 128x128, BK=16, 8 warps, warp tile 64x32.
// A stored in k-permuted smem layout (pos = (c&3)*4 + (c>>2), stride 16)
// so each thread's A fragments for BOTH k8 substeps come from ONE LDS.128.
// =====================================================================
template<int EPI>
__global__ void __launch_bounds__(256, 2)
mma_gemm(const float* __restrict__ A, const float* __restrict__ B,
         const float* __restrict__ bias, const float* __restrict__ resid,
         float* __restrict__ C, int K, int N)
{
    __shared__ float As[128 * 16];
    __shared__ float Bs[16 * 136];

    const int tid  = threadIdx.x;
    const int lane = tid & 31;
    const int wid  = tid >> 5;
    const int warp_m = wid & 1;
    const int warp_n = wid >> 1;
    const int r  = lane >> 2;
    const int cf = lane & 3;

    const int bm = blockIdx.y << 7;
    const int bn = blockIdx.x << 7;

    const int arow = tid >> 2;          // + 64
    const int ag   = tid & 3;           // k-quarter

    // ---- load tile s=0 ----
    {
        #pragma unroll
        for (int i = 0; i < 2; i++) {
            float4 av = *(const float4*)(A + (size_t)(bm + arow + i * 64) * K + ag * 4);
            float* dst = As + (arow + i * 64) * 16 + ag;
            dst[0]  = to_tf32(av.x); dst[4]  = to_tf32(av.y);
            dst[8]  = to_tf32(av.z); dst[12] = to_tf32(av.w);
        }
        #pragma unroll
        for (int i = 0; i < 2; i++) {
            int idx = tid + i * 256;
            int brow = idx >> 5, bc = idx & 31;
            float4 bv = *(const float4*)(B + (size_t)brow * N + bn + bc * 4);
            float4 cv = make_float4(to_tf32(bv.x), to_tf32(bv.y), to_tf32(bv.z), to_tf32(bv.w));
            *(float4*)(Bs + brow * 136 + bc * 4) = cv;
        }
    }
    __syncthreads();

    float acc[4][4][4];
    #pragma unroll
    for (int i = 0; i < 4; i++)
        #pragma unroll
        for (int j = 0; j < 4; j++)
            #pragma unroll
            for (int p = 0; p < 4; p++) acc[i][j][p] = 0.0f;

    const int nsteps = K >> 4;
    float4 aReg[2], bReg[2];
    for (int s = 0; s < nsteps; s++) {
        const bool has_next = (s + 1) < nsteps;
        const int knext = (s + 1) << 4;
        if (has_next) {
            #pragma unroll
            for (int i = 0; i < 2; i++)
                aReg[i] = *(const float4*)(A + (size_t)(bm + arow + i * 64) * K + knext + ag * 4);
            #pragma unroll
            for (int i = 0; i < 2; i++) {
                int idx = tid + i * 256;
                int brow = idx >> 5, bc = idx & 31;
                bReg[i] = *(const float4*)(B + (size_t)(knext + brow) * N + bn + bc * 4);
            }
        }

        // A fragments for both k8 substeps: one LDS.128 per (mtile, rowhalf)
        float4 af[4][2];
        #pragma unroll
        for (int i = 0; i < 4; i++) {
            int m = warp_m * 64 + i * 16;
            af[i][0] = *(const float4*)(As + (m + r) * 16 + cf * 4);
            af[i][1] = *(const float4*)(As + (m + 8 + r) * 16 + cf * 4);
        }
        #pragma unroll
        for (int k8 = 0; k8 < 2; k8++) {
            uint32_t afr[4][4];
            #pragma unroll
            for (int i = 0; i < 4; i++) {
                if (k8 == 0) {
                    afr[i][0] = f2u(af[i][0].x); afr[i][1] = f2u(af[i][1].x);
                    afr[i][2] = f2u(af[i][0].y); afr[i][3] = f2u(af[i][1].y);
                } else {
                    afr[i][0] = f2u(af[i][0].z); afr[i][1] = f2u(af[i][1].z);
                    afr[i][2] = f2u(af[i][0].w); afr[i][3] = f2u(af[i][1].w);
                }
            }
            const int kc = k8 * 8 + cf;
            uint32_t bfr[4][2];
            #pragma unroll
            for (int j = 0; j < 4; j++) {
                int n = warp_n * 32 + j * 8 + r;
                bfr[j][0] = f2u(Bs[kc * 136 + n]);
                bfr[j][1] = f2u(Bs[(kc + 4) * 136 + n]);
            }
            #pragma unroll
            for (int i = 0; i < 4; i++)
                #pragma unroll
                for (int j = 0; j < 4; j++)
                    mma_tf32(acc[i][j], afr[i], bfr[j]);
        }

        if (has_next) {
            __syncthreads();
            #pragma unroll
            for (int i = 0; i < 2; i++) {
                float* dst = As + (arow + i * 64) * 16 + ag;
                dst[0]  = to_tf32(aReg[i].x); dst[4]  = to_tf32(aReg[i].y);
                dst[8]  = to_tf32(aReg[i].z); dst[12] = to_tf32(aReg[i].w);
            }
            #pragma unroll
            for (int i = 0; i < 2; i++) {
                int idx = tid + i * 256;
                int brow = idx >> 5, bc = idx & 31;
                float4 cv = make_float4(to_tf32(bReg[i].x), to_tf32(bReg[i].y),
                                        to_tf32(bReg[i].z), to_tf32(bReg[i].w));
                *(float4*)(Bs + brow * 136 + bc * 4) = cv;
            }
            __syncthreads();
        }
    }

    // -------- epilogue + store --------
    #pragma unroll
    for (int i = 0; i < 4; i++) {
        #pragma unroll
        for (int j = 0; j < 4; j++) {
            int gr0 = bm + warp_m * 64 + i * 16 + r;
            int gc  = bn + warp_n * 32 + j * 8 + cf * 2;
            float v00 = acc[i][j][0], v01 = acc[i][j][1];
            float v10 = acc[i][j][2], v11 = acc[i][j][3];
            float b0 = bias[gc], b1 = bias[gc + 1];
            v00 += b0; v01 += b1; v10 += b0; v11 += b1;
            if (EPI == 1) {
                v00 = 0.5f * v00 * (1.0f + erff(v00 * 0.7071067811865476f));
                v01 = 0.5f * v01 * (1.0f + erff(v01 * 0.7071067811865476f));
                v10 = 0.5f * v10 * (1.0f + erff(v10 * 0.7071067811865476f));
                v11 = 0.5f * v11 * (1.0f + erff(v11 * 0.7071067811865476f));
            }
            if (EPI == 2) {
                v00 += resid[(size_t)gr0 * N + gc];
                v01 += resid[(size_t)gr0 * N + gc + 1];
                v10 += resid[(size_t)(gr0 + 8) * N + gc];
                v11 += resid[(size_t)(gr0 + 8) * N + gc + 1];
            }
            *(float2*)(C + (size_t)gr0 * N + gc)       = make_float2(v00, v01);
            *(float2*)(C + (size_t)(gr0 + 8) * N + gc) = make_float2(v10, v11);
        }
    }
}

// =====================================================================
// Fused attention: per CTA = one (b,h) and a 64-row q block.
// Loads Q (perm layout), K (perm layout), scores via MMA -> smem,
// softmax in smem, V -> smem, PV via MMA -> ctx. Probs never hit gmem.
// dyn smem floats: Qs 4096 | KV 18432 | Ps 64*260=16640 | ids 256
// =====================================================================
#define ATTN_SMEM_FLOATS (4096 + 18432 + 16640 + 256)
#define ATTN_SMEM_BYTES  (ATTN_SMEM_FLOATS * 4)

__global__ void __launch_bounds__(256)
attn_fused(const float* __restrict__ q, const float* __restrict__ k,
           const float* __restrict__ v, const int* __restrict__ ids,
           float* __restrict__ ctx)
{
    extern __shared__ float sm[];
    float* Qs = sm;                    // [4 blk][64 row][16]  perm
    float* KV = sm + 4096;             // K: [4 blk][256 row][16] perm ; V: [256][72]
    float* Ps = sm + 4096 + 18432;     // [64][260]
    int*   ids_s = (int*)(sm + 4096 + 18432 + 16640);

    const int tid  = threadIdx.x;
    const int lane = tid & 31;
    const int wid  = tid >> 5;
    const int r  = lane >> 2;
    const int cf = lane & 3;

    const int qb = blockIdx.x;                 // 0..3
    const int bh = blockIdx.y;                 // 0..1023
    const int b  = bh >> 2, h = bh & 3;

    const float* Qg = q + (size_t)b * SS * DD + h * DHH + (size_t)qb * 64 * DD;
    const float* Kg = k + (size_t)b * SS * DD + h * DHH;
    const float* Vg = v + (size_t)b * SS * DD + h * DHH;
    float* Cg = ctx + (size_t)b * SS * DD + h * DHH + (size_t)qb * 64 * DD;
    const int* idb = ids + b * SS;

    // ---- stage ids ----
    ids_s[tid] = idb[tid];

    // ---- load Q (64x64) into perm layout ----
    {
        int row = tid >> 2, g = tid & 3;
        #pragma unroll
        for (int blk = 0; blk < 4; blk++) {
            float4 qv = *(const float4*)(Qg + (size_t)row * DD + blk * 16 + g * 4);
            float* dst = Qs + blk * 1024 + row * 16 + g;
            dst[0]  = to_tf32(qv.x); dst[4]  = to_tf32(qv.y);
            dst[8]  = to_tf32(qv.z); dst[12] = to_tf32(qv.w);
        }
    }
    // ---- load K (256x64) into perm layout ----
    {
        int g = tid & 3;
        #pragma unroll
        for (int rp = 0; rp < 4; rp++) {
            int row = (tid >> 2) + rp * 64;
            #pragma unroll
            for (int blk = 0; blk < 4; blk++) {
                float4 kv = *(const float4*)(Kg + (size_t)row * DD + blk * 16 + g * 4);
                float* dst = KV + blk * 4096 + row * 16 + g;
                dst[0]  = to_tf32(kv.x); dst[4]  = to_tf32(kv.y);
                dst[8]  = to_tf32(kv.z); dst[12] = to_tf32(kv.w);
            }
        }
    }
    __syncthreads();

    // ---- Phase 1: scores (64x256). warp: wm=wid&3 rows wm*16; wn=wid>>2 cols wn*128 ----
    {
        const int wm = wid & 3, wn = wid >> 2;
        float acc[16][4];
        #pragma unroll
        for (int j = 0; j < 16; j++)
            #pragma unroll
            for (int p = 0; p < 4; p++) acc[j][p] = 0.0f;

        #pragma unroll
        for (int blk = 0; blk < 4; blk++) {
            float4 aq0 = *(const float4*)(Qs + blk * 1024 + (wm * 16 + r) * 16 + cf * 4);
            float4 aq1 = *(const float4*)(Qs + blk * 1024 + (wm * 16 + 8 + r) * 16 + cf * 4);
            uint32_t a0[4] = { f2u(aq0.x), f2u(aq1.x), f2u(aq0.y), f2u(aq1.y) };
            uint32_t a1[4] = { f2u(aq0.z), f2u(aq1.z), f2u(aq0.w), f2u(aq1.w) };
            #pragma unroll
            for (int j = 0; j < 16; j++) {
                int n = wn * 128 + j * 8 + r;
                float4 bq = *(const float4*)(KV + blk * 4096 + n * 16 + cf * 4);
                uint32_t b0[2] = { f2u(bq.x), f2u(bq.y) };
                uint32_t b1[2] = { f2u(bq.z), f2u(bq.w) };
                mma_tf32(acc[j], a0, b0);
                mma_tf32(acc[j], a1, b1);
            }
        }

        const int lrow0 = wm * 16 + r;
        const int grow0 = qb * 64 + lrow0;
        #pragma unroll
        for (int j = 0; j < 16; j++) {
            int gc = wn * 128 + j * 8 + cf * 2;
            bool ok0 = ids_s[gc] > 0, ok1 = ids_s[gc + 1] > 0;
            float v00 = acc[j][0] * 0.125f + ((ok0 && gc     <= grow0    ) ? 0.0f : -10000.0f);
            float v01 = acc[j][1] * 0.125f + ((ok1 && gc + 1 <= grow0    ) ? 0.0f : -10000.0f);
            float v10 = acc[j][2] * 0.125f + ((ok0 && gc     <= grow0 + 8) ? 0.0f : -10000.0f);
            float v11 = acc[j][3] * 0.125f + ((ok1 && gc + 1 <= grow0 + 8) ? 0.0f : -10000.0f);
            *(float2*)(Ps + lrow0 * 260 + gc)       = make_float2(v00, v01);
            *(float2*)(Ps + (lrow0 + 8) * 260 + gc) = make_float2(v10, v11);
        }
    }
    __syncthreads();

    // ---- Phase 2: softmax (4 lanes per row, columns strided by 4 -> conflict-free) ----
    {
        int row = tid >> 2, g = tid & 3;
        float* pr = Ps + row * 260;
        float m = -1e30f;
        #pragma unroll
        for (int c = 0; c < 64; c++) m = fmaxf(m, pr[g + c * 4]);
        m = fmaxf(m, __shfl_xor_sync(0xFFFFFFFFu, m, 1));
        m = fmaxf(m, __shfl_xor_sync(0xFFFFFFFFu, m, 2));
        float s = 0.0f;
        #pragma unroll
        for (int c = 0; c < 64; c++) {
            float e = __expf(pr[g + c * 4] - m);
            pr[g + c * 4] = e;
            s += e;
        }
        s += __shfl_xor_sync(0xFFFFFFFFu, s, 1);
        s += __shfl_xor_sync(0xFFFFFFFFu, s, 2);
        float inv = 1.0f / s;
        #pragma unroll
        for (int c = 0; c < 64; c++) pr[g + c * 4] = to_tf32(pr[g + c * 4] * inv);
    }
    __syncthreads();

    // ---- Phase 3: load V [256][72] (overwrites K) ----
    {
        int g = tid & 3;
        #pragma unroll
        for (int rp = 0; rp < 4; rp++) {
            int row = (tid >> 2) + rp * 64;
            #pragma unroll
            for (int jj = 0; jj < 4; jj++) {
                float4 vv = *(const float4*)(Vg + (size_t)row * DD + (g + jj * 4) * 4);
                float4 cv = make_float4(to_tf32(vv.x), to_tf32(vv.y), to_tf32(vv.z), to_tf32(vv.w));
                *(float4*)(KV + row * 72 + (g + jj * 4) * 4) = cv;
            }
        }
    }
    __syncthreads();

    // ---- Phase 4: PV (64x256 @ 256x64). warp: wm rows 16, wn cols 32 ----
    {
        const int wm = wid & 3, wn = wid >> 2;
        float acc[4][4];
        #pragma unroll
        for (int j = 0; j < 4; j++)
            #pragma unroll
            for (int p = 0; p < 4; p++) acc[j][p] = 0.0f;

        #pragma unroll 4
        for (int k8 = 0; k8 < 32; k8++) {
            const int kc = k8 * 8 + cf;
            uint32_t afr[4];
            afr[0] = f2u(Ps[(wm * 16 + r) * 260 + kc]);
            afr[1] = f2u(Ps[(wm * 16 + 8 + r) * 260 + kc]);
            afr[2] = f2u(Ps[(wm * 16 + r) * 260 + kc + 4]);
            afr[3] = f2u(Ps[(wm * 16 + 8 + r) * 260 + kc + 4]);
            #pragma unroll
            for (int j = 0; j < 4; j++) {
                int n = wn * 32 + j * 8 + r;
                uint32_t bfr[2];
                bfr[0] = f2u(KV[kc * 72 + n]);
                bfr[1] = f2u(KV[(kc + 4) * 72 + n]);
                mma_tf32(acc[j], afr, bfr);
            }
        }

        #pragma unroll
        for (int j = 0; j < 4; j++) {
            int lrow = wm * 16 + r;
            int gc   = wn * 32 + j * 8 + cf * 2;
            *(float2*)(Cg + (size_t)lrow * DD + gc)       = make_float2(acc[j][0], acc[j][1]);
            *(float2*)(Cg + (size_t)(lrow + 8) * DD + gc) = make_float2(acc[j][2], acc[j][3]);
        }
    }
}

// ---------------- host orchestration ----------------
extern "C" void kernel_launch(void* const* d_in, const int* in_sizes, int n_in,
                              void* d_out, int out_size) {
    const int*   ids      = (const int*)  d_in[0];
    const float* item_emb = (const float*)d_in[1];
    const float* pos_emb  = (const float*)d_in[2];
    const float* Wq = (const float*)d_in[3];
    const float* bq = (const float*)d_in[4];
    const float* Wk = (const float*)d_in[5];
    const float* bk = (const float*)d_in[6];
    const float* Wv = (const float*)d_in[7];
    const float* bv = (const float*)d_in[8];
    const float* Wo = (const float*)d_in[9];
    const float* bo = (const float*)d_in[10];
    const float* W1 = (const float*)d_in[11];
    const float* b1 = (const float*)d_in[12];
    const float* W2 = (const float*)d_in[13];
    const float* b2 = (const float*)d_in[14];
    float* out = (float*)d_out;

    float *x, *q, *k, *v, *ctx, *tmp, *h, *mid;
    cudaGetSymbolAddress((void**)&x,   g_x);
    cudaGetSymbolAddress((void**)&q,   g_q);
    cudaGetSymbolAddress((void**)&k,   g_k);
    cudaGetSymbolAddress((void**)&v,   g_v);
    cudaGetSymbolAddress((void**)&ctx, g_ctx);
    cudaGetSymbolAddress((void**)&tmp, g_tmp);
    cudaGetSymbolAddress((void**)&h,   g_h);
    cudaGetSymbolAddress((void**)&mid, g_mid);

    cudaFuncSetAttribute(attn_fused, cudaFuncAttributeMaxDynamicSharedMemorySize,
                         ATTN_SMEM_BYTES);

    embed_ln_kernel<<<MM, 256>>>(ids, item_emb, pos_emb, x, out);

    dim3 gProj(DD / 128, MM / 128);     // (2, 512)
    dim3 gFF1(FF / 128, MM / 128);      // (8, 512)
    dim3 gAttn(SS / 64, BB * HH);       // (4, 1024)

    for (int l = 0; l < LL; l++) {
        const float* Wql = Wq + (size_t)l * DD * DD; const float* bql = bq + l * DD;
        const float* Wkl = Wk + (size_t)l * DD * DD; const float* bkl = bk + l * DD;
        const float* Wvl = Wv + (size_t)l * DD * DD; const float* bvl = bv + l * DD;
        const float* Wol = Wo + (size_t)l * DD * DD; const float* bol = bo + l * DD;
        const float* W1l = W1 + (size_t)l * DD * FF; const float* b1l = b1 + l * FF;
        const float* W2l = W2 + (size_t)l * FF * DD; const float* b2l = b2 + l * DD;

        mma_gemm<0><<<gProj, 256>>>(x, Wql, bql, nullptr, q, DD, DD);
        mma_gemm<0><<<gProj, 256>>>(x, Wkl, bkl, nullptr, k, DD, DD);
        mma_gemm<0><<<gProj, 256>>>(x, Wvl, bvl, nullptr, v, DD, DD);

        attn_fused<<<gAttn, 256, ATTN_SMEM_BYTES>>>(q, k, v, ids, ctx);

        mma_gemm<2><<<gProj, 256>>>(ctx, Wol, bol, x, tmp, DD, DD);
        ln_kernel<<<MM, 256>>>(tmp, h);

        mma_gemm<1><<<gFF1, 256>>>(h, W1l, b1l, nullptr, mid, DD, FF);
        mma_gemm<0><<<gProj, 256>>>(mid, W2l, b2l, nullptr, tmp, FF, DD);
        ln_accum_kernel<<<MM, 256>>>(tmp, x, out);
    }
}

// round 4
// speedup vs baseline: 2.7180x; 1.0859x over previous
#include <cuda_runtime.h>
#include <math.h>
#include <stdint.h>

#define BB 256
#define SS 256
#define DD 256
#define HH 4
#define DHH 64
#define LL 2
#define MM (BB*SS)          // 65536
#define FF (4*DD)           // 1024

// ---------------- scratch (no malloc allowed) ----------------
__device__ float g_x   [ (size_t)MM*DD ];   // fp32 (residual)
__device__ float g_xt  [ (size_t)MM*DD ];   // tf32 perm
__device__ float g_q   [ (size_t)MM*DD ];   // tf32 perm
__device__ float g_k   [ (size_t)MM*DD ];   // tf32 perm
__device__ float g_v   [ (size_t)MM*DD ];   // tf32 plain
__device__ float g_ctxt[ (size_t)MM*DD ];   // tf32 perm
__device__ float g_tmp [ (size_t)MM*DD ];   // fp32
__device__ float g_ht  [ (size_t)MM*DD ];   // tf32 perm
__device__ float g_midt[ (size_t)MM*FF ];   // tf32 perm
__device__ float g_wt  [ (size_t)LL*786432 ]; // converted weights

// ---------------- helpers ----------------
__device__ __forceinline__ float block_sum_256(float v, float* sh) {
    int tid = threadIdx.x;
    sh[tid] = v; __syncthreads();
    #pragma unroll
    for (int s = 128; s > 0; s >>= 1) {
        if (tid < s) sh[tid] += sh[tid + s];
        __syncthreads();
    }
    float r = sh[0];
    __syncthreads();
    return r;
}

__device__ __forceinline__ float to_tf32(float x) {
    float r;
    asm("cvt.rna.tf32.f32 %0, %1;" : "=f"(r) : "f"(x));
    return r;
}

__device__ __forceinline__ void mma_tf32(float* d, const uint32_t* a, const uint32_t* b) {
    asm volatile("mma.sync.aligned.m16n8k8.row.col.f32.tf32.tf32.f32 "
        "{%0,%1,%2,%3}, {%4,%5,%6,%7}, {%8,%9}, {%0,%1,%2,%3};"
        : "+f"(d[0]), "+f"(d[1]), "+f"(d[2]), "+f"(d[3])
        : "r"(a[0]), "r"(a[1]), "r"(a[2]), "r"(a[3]), "r"(b[0]), "r"(b[1]));
}

__device__ __forceinline__ uint32_t f2u(float x) { return __float_as_uint(x); }

// perm within 16-col group: self-inverse 4x4 transpose
__device__ __forceinline__ int permcol(int c) {
    return (c & ~15) + ((c & 3) << 2) + ((c >> 2) & 3);
}

__device__ __forceinline__ void cp_async16(uint32_t s, const void* g) {
    asm volatile("cp.async.cg.shared.global [%0], [%1], 16;" :: "r"(s), "l"(g));
}
__device__ __forceinline__ void cp_commit() { asm volatile("cp.async.commit_group;"); }
template<int N_> __device__ __forceinline__ void cp_wait() {
    asm volatile("cp.async.wait_group %0;" :: "n"(N_));
}

// ---------------- weight convert: W[K][N] fp32 -> Wt[N][K] tf32 perm ----------------
__global__ void conv_weight(const float* __restrict__ W, float* __restrict__ Wt,
                            int K, int N) {
    int idx = blockIdx.x * 256 + threadIdx.x;
    if (idx >= N * K) return;
    int n = idx / K, kk = idx % K;
    int base = kk & ~15, p = kk & 15;
    int k = base + ((p & 3) << 2) + (p >> 2);
    Wt[idx] = to_tf32(W[(size_t)k * N + n]);
}

// ---------------- embedding + LN ----------------
__global__ void embed_ln_kernel(const int* __restrict__ ids,
                                const float* __restrict__ item_emb,
                                const float* __restrict__ pos_emb,
                                float* __restrict__ x, float* __restrict__ xt,
                                float* __restrict__ out) {
    __shared__ float sh[256];
    int row = blockIdx.x;
    int s   = row & (SS - 1);
    int tid = threadIdx.x;
    int id  = ids[row];
    float v = item_emb[(size_t)id * DD + tid] + pos_emb[s * DD + tid];
    float mu  = block_sum_256(v, sh) * (1.0f / DD);
    float d   = v - mu;
    float var = block_sum_256(d * d, sh) * (1.0f / DD);
    float o   = d * rsqrtf(var + 1e-5f);
    size_t idx = (size_t)row * DD + tid;
    x[idx] = o;
    out[idx] = o;
    xt[(size_t)row * DD + permcol(tid)] = to_tf32(o);
}

// LN -> tf32 perm only
__global__ void ln_kernel(const float* __restrict__ in, float* __restrict__ outp) {
    __shared__ float sh[256];
    int row = blockIdx.x, tid = threadIdx.x;
    size_t idx = (size_t)row * DD + tid;
    float v = in[idx];
    float mu  = block_sum_256(v, sh) * (1.0f / DD);
    float d   = v - mu;
    float var = block_sum_256(d * d, sh) * (1.0f / DD);
    float o = d * rsqrtf(var + 1e-5f);
    outp[(size_t)row * DD + permcol(tid)] = to_tf32(o);
}

// LN + accumulate: x=LN(in) fp32, xt=tf32 perm, total += x
__global__ void ln_accum_kernel(const float* __restrict__ in, float* __restrict__ x,
                                float* __restrict__ xt, float* __restrict__ total) {
    __shared__ float sh[256];
    int row = blockIdx.x, tid = threadIdx.x;
    size_t idx = (size_t)row * DD + tid;
    float v = in[idx];
    float mu  = block_sum_256(v, sh) * (1.0f / DD);
    float d   = v - mu;
    float var = block_sum_256(d * d, sh) * (1.0f / DD);
    float o = d * rsqrtf(var + 1e-5f);
    x[idx] = o;
    total[idx] += o;
    xt[(size_t)row * DD + permcol(tid)] = to_tf32(o);
}

// =====================================================================
// TF32 tensor-core GEMM v2 with cp.async 3-stage pipeline.
// A: [M][K] tf32, k-contig with perm-16 groups. Bt: [N][K] same layout.
// C[M,N] = A@B + bias (+GELU / +resid)
// OUT: 0=fp32 plain  1=tf32 perm  2=tf32 plain
// Block 128x128, BK=16, 8 warps (warp tile 64x32).
// =====================================================================
template<int OUT, int GELU, int RESID>
__global__ void __launch_bounds__(256, 2)
mma_gemm2(const float* __restrict__ A, const float* __restrict__ Bt,
          const float* __restrict__ bias, const float* __restrict__ resid,
          float* __restrict__ C, int K, int N)
{
    __shared__ float As[3][2048];
    __shared__ float Bs[3][2048];

    const int tid  = threadIdx.x;
    const int lane = tid & 31;
    const int wid  = tid >> 5;
    const int warp_m = wid & 1;
    const int warp_n = wid >> 1;
    const int r  = lane >> 2;
    const int cf = lane & 3;

    const int bm = blockIdx.y << 7;
    const int bn = blockIdx.x << 7;

    const int row0 = tid >> 2;          // 0..63 ; +64 for second
    const int seg  = (tid & 3) << 2;    // 0,4,8,12

    const int nsteps = K >> 4;

    // ---- prologue: stages 0,1 ----
    #pragma unroll
    for (int s = 0; s < 2; s++) {
        uint32_t a0 = (uint32_t)__cvta_generic_to_shared(&As[s][row0 * 16 + seg]);
        uint32_t a1 = (uint32_t)__cvta_generic_to_shared(&As[s][(row0 + 64) * 16 + seg]);
        uint32_t b0 = (uint32_t)__cvta_generic_to_shared(&Bs[s][row0 * 16 + seg]);
        uint32_t b1 = (uint32_t)__cvta_generic_to_shared(&Bs[s][(row0 + 64) * 16 + seg]);
        cp_async16(a0, A  + (size_t)(bm + row0)      * K + s * 16 + seg);
        cp_async16(a1, A  + (size_t)(bm + row0 + 64) * K + s * 16 + seg);
        cp_async16(b0, Bt + (size_t)(bn + row0)      * K + s * 16 + seg);
        cp_async16(b1, Bt + (size_t)(bn + row0 + 64) * K + s * 16 + seg);
        cp_commit();
    }

    float acc[4][4][4];
    #pragma unroll
    for (int i = 0; i < 4; i++)
        #pragma unroll
        for (int j = 0; j < 4; j++)
            #pragma unroll
            for (int p = 0; p < 4; p++) acc[i][j][p] = 0.0f;

    for (int s = 0; s < nsteps; s++) {
        if (s + 1 < nsteps) cp_wait<1>(); else cp_wait<0>();
        __syncthreads();

        // refill oldest buffer (safe: all warps finished compute(s-1) at the sync)
        if (s + 2 < nsteps) {
            int buf = (s + 2) % 3;
            uint32_t a0 = (uint32_t)__cvta_generic_to_shared(&As[buf][row0 * 16 + seg]);
            uint32_t a1 = (uint32_t)__cvta_generic_to_shared(&As[buf][(row0 + 64) * 16 + seg]);
            uint32_t b0 = (uint32_t)__cvta_generic_to_shared(&Bs[buf][row0 * 16 + seg]);
            uint32_t b1 = (uint32_t)__cvta_generic_to_shared(&Bs[buf][(row0 + 64) * 16 + seg]);
            cp_async16(a0, A  + (size_t)(bm + row0)      * K + (s + 2) * 16 + seg);
            cp_async16(a1, A  + (size_t)(bm + row0 + 64) * K + (s + 2) * 16 + seg);
            cp_async16(b0, Bt + (size_t)(bn + row0)      * K + (s + 2) * 16 + seg);
            cp_async16(b1, Bt + (size_t)(bn + row0 + 64) * K + (s + 2) * 16 + seg);
            cp_commit();
        }

        const int buf = s % 3;
        float4 af[4][2];
        #pragma unroll
        for (int i = 0; i < 4; i++) {
            int m = warp_m * 64 + i * 16;
            af[i][0] = *(const float4*)(&As[buf][(m + r) * 16 + cf * 4]);
            af[i][1] = *(const float4*)(&As[buf][(m + 8 + r) * 16 + cf * 4]);
        }
        float4 bf[4];
        #pragma unroll
        for (int j = 0; j < 4; j++) {
            int n = warp_n * 32 + j * 8 + r;
            bf[j] = *(const float4*)(&Bs[buf][n * 16 + cf * 4]);
        }

        // k8 = 0
        {
            uint32_t afr[4][4], bfr[4][2];
            #pragma unroll
            for (int i = 0; i < 4; i++) {
                afr[i][0] = f2u(af[i][0].x); afr[i][1] = f2u(af[i][1].x);
                afr[i][2] = f2u(af[i][0].y); afr[i][3] = f2u(af[i][1].y);
            }
            #pragma unroll
            for (int j = 0; j < 4; j++) { bfr[j][0] = f2u(bf[j].x); bfr[j][1] = f2u(bf[j].y); }
            #pragma unroll
            for (int i = 0; i < 4; i++)
                #pragma unroll
                for (int j = 0; j < 4; j++)
                    mma_tf32(acc[i][j], afr[i], bfr[j]);
        }
        // k8 = 1
        {
            uint32_t afr[4][4], bfr[4][2];
            #pragma unroll
            for (int i = 0; i < 4; i++) {
                afr[i][0] = f2u(af[i][0].z); afr[i][1] = f2u(af[i][1].z);
                afr[i][2] = f2u(af[i][0].w); afr[i][3] = f2u(af[i][1].w);
            }
            #pragma unroll
            for (int j = 0; j < 4; j++) { bfr[j][0] = f2u(bf[j].z); bfr[j][1] = f2u(bf[j].w); }
            #pragma unroll
            for (int i = 0; i < 4; i++)
                #pragma unroll
                for (int j = 0; j < 4; j++)
                    mma_tf32(acc[i][j], afr[i], bfr[j]);
        }
    }

    // -------- epilogue + store --------
    #pragma unroll
    for (int i = 0; i < 4; i++) {
        #pragma unroll
        for (int j = 0; j < 4; j++) {
            int gr0 = bm + warp_m * 64 + i * 16 + r;
            int gc  = bn + warp_n * 32 + j * 8 + cf * 2;
            float v00 = acc[i][j][0], v01 = acc[i][j][1];
            float v10 = acc[i][j][2], v11 = acc[i][j][3];
            float b0 = bias[gc], b1 = bias[gc + 1];
            v00 += b0; v01 += b1; v10 += b0; v11 += b1;
            if (GELU) {
                v00 = 0.5f * v00 * (1.0f + erff(v00 * 0.7071067811865476f));
                v01 = 0.5f * v01 * (1.0f + erff(v01 * 0.7071067811865476f));
                v10 = 0.5f * v10 * (1.0f + erff(v10 * 0.7071067811865476f));
                v11 = 0.5f * v11 * (1.0f + erff(v11 * 0.7071067811865476f));
            }
            if (RESID) {
                v00 += resid[(size_t)gr0 * N + gc];
                v01 += resid[(size_t)gr0 * N + gc + 1];
                v10 += resid[(size_t)(gr0 + 8) * N + gc];
                v11 += resid[(size_t)(gr0 + 8) * N + gc + 1];
            }
            if (OUT == 0) {
                *(float2*)(C + (size_t)gr0 * N + gc)       = make_float2(v00, v01);
                *(float2*)(C + (size_t)(gr0 + 8) * N + gc) = make_float2(v10, v11);
            } else if (OUT == 1) {
                int c0 = permcol(gc), c1 = permcol(gc + 1);
                C[(size_t)gr0 * N + c0]       = to_tf32(v00);
                C[(size_t)gr0 * N + c1]       = to_tf32(v01);
                C[(size_t)(gr0 + 8) * N + c0] = to_tf32(v10);
                C[(size_t)(gr0 + 8) * N + c1] = to_tf32(v11);
            } else {
                *(float2*)(C + (size_t)gr0 * N + gc)       = make_float2(to_tf32(v00), to_tf32(v01));
                *(float2*)(C + (size_t)(gr0 + 8) * N + gc) = make_float2(to_tf32(v10), to_tf32(v11));
            }
        }
    }
}

// =====================================================================
// Fused attention (q,k: tf32 perm gmem; v: tf32 plain gmem).
// dyn smem floats: Qs 4096 | KV 18432 | Ps 64*260=16640 | ids 256
// =====================================================================
#define ATTN_SMEM_FLOATS (4096 + 18432 + 16640 + 256)
#define ATTN_SMEM_BYTES  (ATTN_SMEM_FLOATS * 4)

__global__ void __launch_bounds__(256)
attn_fused(const float* __restrict__ q, const float* __restrict__ k,
           const float* __restrict__ v, const int* __restrict__ ids,
           float* __restrict__ ctxt)
{
    extern __shared__ float sm[];
    float* Qs = sm;                    // [4 blk][64 row][16]  perm
    float* KV = sm + 4096;             // K: [4 blk][256 row][16] perm ; V: [256][72]
    float* Ps = sm + 4096 + 18432;     // [64][260]
    int*   ids_s = (int*)(sm + 4096 + 18432 + 16640);

    const int tid  = threadIdx.x;
    const int lane = tid & 31;
    const int wid  = tid >> 5;
    const int r  = lane >> 2;
    const int cf = lane & 3;

    const int qb = blockIdx.x;
    const int bh = blockIdx.y;
    const int b  = bh >> 2, h = bh & 3;

    const float* Qg = q + (size_t)b * SS * DD + h * DHH + (size_t)qb * 64 * DD;
    const float* Kg = k + (size_t)b * SS * DD + h * DHH;
    const float* Vg = v + (size_t)b * SS * DD + h * DHH;
    float* Cg = ctxt + (size_t)b * SS * DD + h * DHH + (size_t)qb * 64 * DD;
    const int* idb = ids + b * SS;

    ids_s[tid] = idb[tid];

    // Q: straight float4 copies (already tf32 perm)
    {
        int row = tid >> 2, g = tid & 3;
        #pragma unroll
        for (int blk = 0; blk < 4; blk++) {
            float4 qv = *(const float4*)(Qg + (size_t)row * DD + blk * 16 + g * 4);
            *(float4*)(Qs + blk * 1024 + row * 16 + g * 4) = qv;
        }
    }
    // K
    {
        int g = tid & 3;
        #pragma unroll
        for (int rp = 0; rp < 4; rp++) {
            int row = (tid >> 2) + rp * 64;
            #pragma unroll
            for (int blk = 0; blk < 4; blk++) {
                float4 kv = *(const float4*)(Kg + (size_t)row * DD + blk * 16 + g * 4);
                *(float4*)(KV + blk * 4096 + row * 16 + g * 4) = kv;
            }
        }
    }
    __syncthreads();

    // ---- Phase 1: scores ----
    {
        const int wm = wid & 3, wn = wid >> 2;
        float acc[16][4];
        #pragma unroll
        for (int j = 0; j < 16; j++)
            #pragma unroll
            for (int p = 0; p < 4; p++) acc[j][p] = 0.0f;

        #pragma unroll
        for (int blk = 0; blk < 4; blk++) {
            float4 aq0 = *(const float4*)(Qs + blk * 1024 + (wm * 16 + r) * 16 + cf * 4);
            float4 aq1 = *(const float4*)(Qs + blk * 1024 + (wm * 16 + 8 + r) * 16 + cf * 4);
            uint32_t a0[4] = { f2u(aq0.x), f2u(aq1.x), f2u(aq0.y), f2u(aq1.y) };
            uint32_t a1[4] = { f2u(aq0.z), f2u(aq1.z), f2u(aq0.w), f2u(aq1.w) };
            #pragma unroll
            for (int j = 0; j < 16; j++) {
                int n = wn * 128 + j * 8 + r;
                float4 bq = *(const float4*)(KV + blk * 4096 + n * 16 + cf * 4);
                uint32_t b0[2] = { f2u(bq.x), f2u(bq.y) };
                uint32_t b1[2] = { f2u(bq.z), f2u(bq.w) };
                mma_tf32(acc[j], a0, b0);
                mma_tf32(acc[j], a1, b1);
            }
        }

        const int lrow0 = wm * 16 + r;
        const int grow0 = qb * 64 + lrow0;
        #pragma unroll
        for (int j = 0; j < 16; j++) {
            int gc = wn * 128 + j * 8 + cf * 2;
            bool ok0 = ids_s[gc] > 0, ok1 = ids_s[gc + 1] > 0;
            float v00 = acc[j][0] * 0.125f + ((ok0 && gc     <= grow0    ) ? 0.0f : -10000.0f);
            float v01 = acc[j][1] * 0.125f + ((ok1 && gc + 1 <= grow0    ) ? 0.0f : -10000.0f);
            float v10 = acc[j][2] * 0.125f + ((ok0 && gc     <= grow0 + 8) ? 0.0f : -10000.0f);
            float v11 = acc[j][3] * 0.125f + ((ok1 && gc + 1 <= grow0 + 8) ? 0.0f : -10000.0f);
            *(float2*)(Ps + lrow0 * 260 + gc)       = make_float2(v00, v01);
            *(float2*)(Ps + (lrow0 + 8) * 260 + gc) = make_float2(v10, v11);
        }
    }
    __syncthreads();

    // ---- Phase 2: softmax ----
    {
        int row = tid >> 2, g = tid & 3;
        float* pr = Ps + row * 260;
        float m = -1e30f;
        #pragma unroll
        for (int c = 0; c < 64; c++) m = fmaxf(m, pr[g + c * 4]);
        m = fmaxf(m, __shfl_xor_sync(0xFFFFFFFFu, m, 1));
        m = fmaxf(m, __shfl_xor_sync(0xFFFFFFFFu, m, 2));
        float s = 0.0f;
        #pragma unroll
        for (int c = 0; c < 64; c++) {
            float e = __expf(pr[g + c * 4] - m);
            pr[g + c * 4] = e;
            s += e;
        }
        s += __shfl_xor_sync(0xFFFFFFFFu, s, 1);
        s += __shfl_xor_sync(0xFFFFFFFFu, s, 2);
        float inv = 1.0f / s;
        #pragma unroll
        for (int c = 0; c < 64; c++) pr[g + c * 4] = to_tf32(pr[g + c * 4] * inv);
    }
    __syncthreads();

    // ---- Phase 3: V (plain tf32) -> [256][72] ----
    {
        int g = tid & 3;
        #pragma unroll
        for (int rp = 0; rp < 4; rp++) {
            int row = (tid >> 2) + rp * 64;
            #pragma unroll
            for (int jj = 0; jj < 4; jj++) {
                float4 vv = *(const float4*)(Vg + (size_t)row * DD + (g + jj * 4) * 4);
                *(float4*)(KV + row * 72 + (g + jj * 4) * 4) = vv;
            }
        }
    }
    __syncthreads();

    // ---- Phase 4: PV ----
    {
        const int wm = wid & 3, wn = wid >> 2;
        float acc[4][4];
        #pragma unroll
        for (int j = 0; j < 4; j++)
            #pragma unroll
            for (int p = 0; p < 4; p++) acc[j][p] = 0.0f;

        #pragma unroll 4
        for (int k8 = 0; k8 < 32; k8++) {
            const int kc = k8 * 8 + cf;
            uint32_t afr[4];
            afr[0] = f2u(Ps[(wm * 16 + r) * 260 + kc]);
            afr[1] = f2u(Ps[(wm * 16 + 8 + r) * 260 + kc]);
            afr[2] = f2u(Ps[(wm * 16 + r) * 260 + kc + 4]);
            afr[3] = f2u(Ps[(wm * 16 + 8 + r) * 260 + kc + 4]);
            #pragma unroll
            for (int j = 0; j < 4; j++) {
                int n = wn * 32 + j * 8 + r;
                uint32_t bfr[2];
                bfr[0] = f2u(KV[kc * 72 + n]);
                bfr[1] = f2u(KV[(kc + 4) * 72 + n]);
                mma_tf32(acc[j], afr, bfr);
            }
        }

        // write ctxt: tf32 perm
        #pragma unroll
        for (int j = 0; j < 4; j++) {
            int lrow = wm * 16 + r;
            int gc   = wn * 32 + j * 8 + cf * 2;     // local col within 64 (16-aligned groups)
            int c0 = permcol(gc), c1 = permcol(gc + 1);
            Cg[(size_t)lrow * DD + c0]       = to_tf32(acc[j][0]);
            Cg[(size_t)lrow * DD + c1]       = to_tf32(acc[j][1]);
            Cg[(size_t)(lrow + 8) * DD + c0] = to_tf32(acc[j][2]);
            Cg[(size_t)(lrow + 8) * DD + c1] = to_tf32(acc[j][3]);
        }
    }
}

// ---------------- host orchestration ----------------
extern "C" void kernel_launch(void* const* d_in, const int* in_sizes, int n_in,
                              void* d_out, int out_size) {
    const int*   ids      = (const int*)  d_in[0];
    const float* item_emb = (const float*)d_in[1];
    const float* pos_emb  = (const float*)d_in[2];
    const float* Wq = (const float*)d_in[3];
    const float* bq = (const float*)d_in[4];
    const float* Wk = (const float*)d_in[5];
    const float* bk = (const float*)d_in[6];
    const float* Wv = (const float*)d_in[7];
    const float* bv = (const float*)d_in[8];
    const float* Wo = (const float*)d_in[9];
    const float* bo = (const float*)d_in[10];
    const float* W1 = (const float*)d_in[11];
    const float* b1 = (const float*)d_in[12];
    const float* W2 = (const float*)d_in[13];
    const float* b2 = (const float*)d_in[14];
    float* out = (float*)d_out;

    float *x, *xt, *q, *k, *v, *ctxt, *tmp, *ht, *midt, *wt;
    cudaGetSymbolAddress((void**)&x,    g_x);
    cudaGetSymbolAddress((void**)&xt,   g_xt);
    cudaGetSymbolAddress((void**)&q,    g_q);
    cudaGetSymbolAddress((void**)&k,    g_k);
    cudaGetSymbolAddress((void**)&v,    g_v);
    cudaGetSymbolAddress((void**)&ctxt, g_ctxt);
    cudaGetSymbolAddress((void**)&tmp,  g_tmp);
    cudaGetSymbolAddress((void**)&ht,   g_ht);
    cudaGetSymbolAddress((void**)&midt, g_midt);
    cudaGetSymbolAddress((void**)&wt,   g_wt);

    cudaFuncSetAttribute(attn_fused, cudaFuncAttributeMaxDynamicSharedMemorySize,
                         ATTN_SMEM_BYTES);

    // ---- convert weights: per layer offsets into wt ----
    // Wq 0 | Wk 65536 | Wv 131072 | Wo 196608 | W1 262144 | W2 524288 ; stride 786432
    const int gDDxDD = (DD * DD + 255) / 256;
    const int gDDxFF = (DD * FF + 255) / 256;
    for (int l = 0; l < LL; l++) {
        float* base = wt + (size_t)l * 786432;
        conv_weight<<<gDDxDD, 256>>>(Wq + (size_t)l * DD * DD, base,          DD, DD);
        conv_weight<<<gDDxDD, 256>>>(Wk + (size_t)l * DD * DD, base + 65536,  DD, DD);
        conv_weight<<<gDDxDD, 256>>>(Wv + (size_t)l * DD * DD, base + 131072, DD, DD);
        conv_weight<<<gDDxDD, 256>>>(Wo + (size_t)l * DD * DD, base + 196608, DD, DD);
        conv_weight<<<gDDxFF, 256>>>(W1 + (size_t)l * DD * FF, base + 262144, DD, FF);
        conv_weight<<<gDDxFF, 256>>>(W2 + (size_t)l * FF * DD, base + 524288, FF, DD);
    }

    embed_ln_kernel<<<MM, 256>>>(ids, item_emb, pos_emb, x, xt, out);

    dim3 gProj(DD / 128, MM / 128);     // (2, 512)
    dim3 gFF1(FF / 128, MM / 128);      // (8, 512)
    dim3 gAttn(SS / 64, BB * HH);       // (4, 1024)

    for (int l = 0; l < LL; l++) {
        float* base = wt + (size_t)l * 786432;
        const float* Wqt = base;
        const float* Wkt = base + 65536;
        const float* Wvt = base + 131072;
        const float* Wot = base + 196608;
        const float* W1t = base + 262144;
        const float* W2t = base + 524288;
        const float* bql = bq + l * DD;
        const float* bkl = bk + l * DD;
        const float* bvl = bv + l * DD;
        const float* bol = bo + l * DD;
        const float* b1l = b1 + l * FF;
        const float* b2l = b2 + l * DD;

        mma_gemm2<1,0,0><<<gProj, 256>>>(xt, Wqt, bql, nullptr, q, DD, DD);
        mma_gemm2<1,0,0><<<gProj, 256>>>(xt, Wkt, bkl, nullptr, k, DD, DD);
        mma_gemm2<2,0,0><<<gProj, 256>>>(xt, Wvt, bvl, nullptr, v, DD, DD);

        attn_fused<<<gAttn, 256, ATTN_SMEM_BYTES>>>(q, k, v, ids, ctxt);

        mma_gemm2<0,0,1><<<gProj, 256>>>(ctxt, Wot, bol, x, tmp, DD, DD);
        ln_kernel<<<MM, 256>>>(tmp, ht);

        mma_gemm2<1,1,0><<<gFF1, 256>>>(ht, W1t, b1l, nullptr, midt, DD, FF);
        mma_gemm2<0,0,0><<<gProj, 256>>>(midt, W2t, b2l, nullptr, tmp, FF, DD);
        ln_accum_kernel<<<MM, 256>>>(tmp, x, xt, out);
    }
}

// round 7
// speedup vs baseline: 4.1080x; 1.5114x over previous
#include <cuda_runtime.h>
#include <cuda_fp16.h>
#include <math.h>
#include <stdint.h>

#define BB 256
#define SS 256
#define DD 256
#define HH 4
#define DHH 64
#define LL 2
#define MM (BB*SS)          // 65536
#define FF (4*DD)           // 1024

// ---------------- scratch (no malloc allowed) ----------------
__device__ float g_x  [ (size_t)MM*DD ];                     // fp32 residual
__device__ float g_tmp[ (size_t)MM*DD ];                     // fp32
__device__ __align__(16) __half g_xt  [ (size_t)MM*DD ];     // half activations
__device__ __align__(16) __half g_q   [ (size_t)MM*DD ];
__device__ __align__(16) __half g_k   [ (size_t)MM*DD ];
__device__ __align__(16) __half g_v   [ (size_t)MM*DD ];
__device__ __align__(16) __half g_ctxt[ (size_t)MM*DD ];
__device__ __align__(16) __half g_ht  [ (size_t)MM*DD ];
__device__ __align__(16) __half g_midt[ (size_t)MM*FF ];
__device__ __align__(16) __half g_wt  [ (size_t)LL*786432 ]; // weights [N][K] half

// ---------------- helpers ----------------
__device__ __forceinline__ float block_sum_256(float v, float* sh) {
    int tid = threadIdx.x;
    sh[tid] = v; __syncthreads();
    #pragma unroll
    for (int s = 128; s > 0; s >>= 1) {
        if (tid < s) sh[tid] += sh[tid + s];
        __syncthreads();
    }
    float r = sh[0];
    __syncthreads();
    return r;
}

__device__ __forceinline__ void mma_f16(float* d, const uint32_t* a, const uint32_t* b) {
    asm volatile("mma.sync.aligned.m16n8k16.row.col.f32.f16.f16.f32 "
        "{%0,%1,%2,%3}, {%4,%5,%6,%7}, {%8,%9}, {%0,%1,%2,%3};"
        : "+f"(d[0]), "+f"(d[1]), "+f"(d[2]), "+f"(d[3])
        : "r"(a[0]), "r"(a[1]), "r"(a[2]), "r"(a[3]), "r"(b[0]), "r"(b[1]));
}

__device__ __forceinline__ void ldsm_x4(uint32_t* d, uint32_t a) {
    asm volatile("ldmatrix.sync.aligned.m8n8.x4.shared.b16 {%0,%1,%2,%3}, [%4];"
        : "=r"(d[0]), "=r"(d[1]), "=r"(d[2]), "=r"(d[3]) : "r"(a));
}
__device__ __forceinline__ void ldsm_x4_t(uint32_t* d, uint32_t a) {
    asm volatile("ldmatrix.sync.aligned.m8n8.x4.trans.shared.b16 {%0,%1,%2,%3}, [%4];"
        : "=r"(d[0]), "=r"(d[1]), "=r"(d[2]), "=r"(d[3]) : "r"(a));
}

__device__ __forceinline__ void cp_async16(uint32_t s, const void* g) {
    asm volatile("cp.async.cg.shared.global [%0], [%1], 16;" :: "r"(s), "l"(g));
}
__device__ __forceinline__ void cp_commit() { asm volatile("cp.async.commit_group;"); }
template<int N_> __device__ __forceinline__ void cp_wait() {
    asm volatile("cp.async.wait_group %0;" :: "n"(N_));
}

__device__ __forceinline__ uint32_t smem_u32(const void* p) {
    uint32_t a;
    asm("{ .reg .u64 t; cvta.to.shared.u64 t, %1; cvt.u32.u64 %0, t; }" : "=r"(a) : "l"(p));
    return a;
}

// ---------------- weight convert: W[K][N] fp32 -> Wt[N][K] half ----------------
__global__ void conv_weight(const float* __restrict__ W, __half* __restrict__ Wt,
                            int K, int N) {
    int idx = blockIdx.x * 256 + threadIdx.x;
    if (idx >= N * K) return;
    int n = idx / K, k = idx % K;
    Wt[idx] = __float2half_rn(W[(size_t)k * N + n]);
}

// ---------------- embedding + LN ----------------
__global__ void embed_ln_kernel(const int* __restrict__ ids,
                                const float* __restrict__ item_emb,
                                const float* __restrict__ pos_emb,
                                float* __restrict__ x, __half* __restrict__ xt,
                                float* __restrict__ out) {
    __shared__ float sh[256];
    int row = blockIdx.x;
    int s   = row & (SS - 1);
    int tid = threadIdx.x;
    int id  = ids[row];
    float v = item_emb[(size_t)id * DD + tid] + pos_emb[s * DD + tid];
    float mu  = block_sum_256(v, sh) * (1.0f / DD);
    float d   = v - mu;
    float var = block_sum_256(d * d, sh) * (1.0f / DD);
    float o   = d * rsqrtf(var + 1e-5f);
    size_t idx = (size_t)row * DD + tid;
    x[idx] = o;
    out[idx] = o;
    xt[idx] = __float2half_rn(o);
}

__global__ void ln_kernel(const float* __restrict__ in, __half* __restrict__ outp) {
    __shared__ float sh[256];
    int row = blockIdx.x, tid = threadIdx.x;
    size_t idx = (size_t)row * DD + tid;
    float v = in[idx];
    float mu  = block_sum_256(v, sh) * (1.0f / DD);
    float d   = v - mu;
    float var = block_sum_256(d * d, sh) * (1.0f / DD);
    outp[idx] = __float2half_rn(d * rsqrtf(var + 1e-5f));
}

__global__ void ln_accum_kernel(const float* __restrict__ in, float* __restrict__ x,
                                __half* __restrict__ xt, float* __restrict__ total) {
    __shared__ float sh[256];
    int row = blockIdx.x, tid = threadIdx.x;
    size_t idx = (size_t)row * DD + tid;
    float v = in[idx];
    float mu  = block_sum_256(v, sh) * (1.0f / DD);
    float d   = v - mu;
    float var = block_sum_256(d * d, sh) * (1.0f / DD);
    float o = d * rsqrtf(var + 1e-5f);
    x[idx] = o;
    total[idx] += o;
    xt[idx] = __float2half_rn(o);
}

// =====================================================================
// FP16 tensor-core GEMM: C[M,N] = A[M,K] @ W   (Bt = W^T as [N][K] half)
// 128x128 tile, BK=32, 3-stage cp.async, 8 warps (warp tile 64x32),
// m16n8k16 HMMA, ldmatrix fragments, 80B row stride (conflict-free).
// OUTHALF: 1 -> C is half ; 0 -> C is fp32
// =====================================================================
#define HGEMM_SMEM (3 * 20480)

template<int OUTHALF, int GELU, int RESID>
__global__ void __launch_bounds__(256, 2)
hgemm(const __half* __restrict__ A, const __half* __restrict__ Bt,
      const float* __restrict__ bias, const float* __restrict__ resid,
      void* __restrict__ Cv, int K, int N)
{
    extern __shared__ char smem[];
    const uint32_t sb = smem_u32(smem);

    const int tid  = threadIdx.x;
    const int lane = tid & 31;
    const int wid  = tid >> 5;
    const int warp_m = wid & 1;
    const int warp_n = wid >> 1;
    const int r  = lane >> 2;
    const int cf = lane & 3;
    const int quad = lane >> 3, li = lane & 7;

    const int bm = blockIdx.y << 7;
    const int bn = blockIdx.x << 7;

    // loader: thread covers row (tid>>1), 32B half-chunk (tid&1)
    const int lrow = tid >> 1;
    const int lc   = (tid & 1) * 32;                 // byte offset within 64B chunk
    const __half* Ag = A  + (size_t)(bm + lrow) * K + (lc >> 1);
    const __half* Bg = Bt + (size_t)(bn + lrow) * K + (lc >> 1);
    const uint32_t sA = sb +         lrow * 80 + lc;
    const uint32_t sB = sb + 10240 + lrow * 80 + lc;

    const int nsteps = K >> 5;

    #pragma unroll
    for (int s = 0; s < 2; s++) {
        cp_async16(sA + s * 20480,      Ag + s * 32);
        cp_async16(sA + s * 20480 + 16, Ag + s * 32 + 8);
        cp_async16(sB + s * 20480,      Bg + s * 32);
        cp_async16(sB + s * 20480 + 16, Bg + s * 32 + 8);
        cp_commit();
    }

    // ldmatrix lane-local offsets
    const uint32_t aoff = (uint32_t)((warp_m * 64 + ((quad & 1) << 3) + li) * 80
                                     + ((quad >> 1) << 4));
    const uint32_t boff = (uint32_t)(10240 + (warp_n * 32 + ((quad & 2) ? 8 : 0) + li) * 80
                                     + ((quad & 1) << 4));

    float acc[4][4][4];
    #pragma unroll
    for (int i = 0; i < 4; i++)
        #pragma unroll
        for (int j = 0; j < 4; j++)
            #pragma unroll
            for (int p = 0; p < 4; p++) acc[i][j][p] = 0.0f;

    for (int s = 0; s < nsteps; s++) {
        if (s + 1 < nsteps) cp_wait<1>(); else cp_wait<0>();
        __syncthreads();
        if (s + 2 < nsteps) {
            const uint32_t st = ((s + 2) % 3) * 20480;
            cp_async16(sA + st,      Ag + (s + 2) * 32);
            cp_async16(sA + st + 16, Ag + (s + 2) * 32 + 8);
            cp_async16(sB + st,      Bg + (s + 2) * 32);
            cp_async16(sB + st + 16, Bg + (s + 2) * 32 + 8);
            cp_commit();
        }
        const uint32_t stg = sb + (s % 3) * 20480;

        uint32_t af[2][4][4];
        #pragma unroll
        for (int ks = 0; ks < 2; ks++)
            #pragma unroll
            for (int i = 0; i < 4; i++)
                ldsm_x4(af[ks][i], stg + aoff + i * 1280 + ks * 32);

        #pragma unroll
        for (int ks = 0; ks < 2; ks++) {
            #pragma unroll
            for (int j2 = 0; j2 < 2; j2++) {
                uint32_t bf[4];
                ldsm_x4(bf, stg + boff + j2 * 1280 + ks * 32);
                #pragma unroll
                for (int i = 0; i < 4; i++) {
                    mma_f16(acc[i][2 * j2],     af[ks][i], bf);
                    mma_f16(acc[i][2 * j2 + 1], af[ks][i], bf + 2);
                }
            }
        }
    }

    // -------- epilogue --------
    #pragma unroll
    for (int i = 0; i < 4; i++) {
        #pragma unroll
        for (int j = 0; j < 4; j++) {
            int gr0 = bm + warp_m * 64 + i * 16 + r;
            int gc  = bn + warp_n * 32 + j * 8 + cf * 2;
            float v00 = acc[i][j][0], v01 = acc[i][j][1];
            float v10 = acc[i][j][2], v11 = acc[i][j][3];
            float b0 = bias[gc], b1 = bias[gc + 1];
            v00 += b0; v01 += b1; v10 += b0; v11 += b1;
            if (GELU) {
                v00 = 0.5f * v00 * (1.0f + erff(v00 * 0.7071067811865476f));
                v01 = 0.5f * v01 * (1.0f + erff(v01 * 0.7071067811865476f));
                v10 = 0.5f * v10 * (1.0f + erff(v10 * 0.7071067811865476f));
                v11 = 0.5f * v11 * (1.0f + erff(v11 * 0.7071067811865476f));
            }
            if (RESID) {
                const float* rz = resid;
                v00 += rz[(size_t)gr0 * N + gc];
                v01 += rz[(size_t)gr0 * N + gc + 1];
                v10 += rz[(size_t)(gr0 + 8) * N + gc];
                v11 += rz[(size_t)(gr0 + 8) * N + gc + 1];
            }
            if (OUTHALF) {
                __half* Ch = (__half*)Cv;
                *(__half2*)(Ch + (size_t)gr0 * N + gc)       = __floats2half2_rn(v00, v01);
                *(__half2*)(Ch + (size_t)(gr0 + 8) * N + gc) = __floats2half2_rn(v10, v11);
            } else {
                float* Cf = (float*)Cv;
                *(float2*)(Cf + (size_t)gr0 * N + gc)       = make_float2(v00, v01);
                *(float2*)(Cf + (size_t)(gr0 + 8) * N + gc) = make_float2(v10, v11);
            }
        }
    }
}

// =====================================================================
// Fused FP16 attention. Per CTA: (b,h), 64 q-rows. Scores in registers,
// softmax via shfl + smem rowred, probs half -> PV. All MMA via ldmatrix.
// smem: Qs 64x144B | KV 256x144B (K then V) | Ph 64x528B | red 1KB | ids 1KB
// =====================================================================
#define ATTN_SMEM_BYTES 81920

__global__ void __launch_bounds__(256, 2)
attn_fused(const __half* __restrict__ q, const __half* __restrict__ k,
           const __half* __restrict__ v, const int* __restrict__ ids,
           __half* __restrict__ ctxt)
{
    extern __shared__ char sm[];
    char* Qs = sm;                    // 9216 B
    char* KV = sm + 9216;             // 36864 B
    char* Ph = sm + 46080;            // 33792 B
    float* red   = (float*)(sm + 79872);   // [2][64][2]
    int*   ids_s = (int*)(sm + 80896);

    const int tid  = threadIdx.x;
    const int lane = tid & 31;
    const int wid  = tid >> 5;
    const int r  = lane >> 2;
    const int cf = lane & 3;
    const int quad = lane >> 3, li = lane & 7;

    const int qb = blockIdx.x;
    const int bh = blockIdx.y;
    const int b  = bh >> 2, h = bh & 3;

    const __half* Qg = q + (size_t)b * SS * DD + h * DHH + (size_t)qb * 64 * DD;
    const __half* Kg = k + (size_t)b * SS * DD + h * DHH;
    const __half* Vg = v + (size_t)b * SS * DD + h * DHH;
    __half* Cg = ctxt + (size_t)b * SS * DD + h * DHH + (size_t)qb * 64 * DD;
    const int* idb = ids + b * SS;

    ids_s[tid] = idb[tid];

    // ---- load Q (64 rows x 128B) ----
    {
        int row = tid >> 2, c = (tid & 3) * 32;
        const __half* src = Qg + (size_t)row * DD + (c >> 1);
        *(float4*)(Qs + row * 144 + c)      = *(const float4*)(src);
        *(float4*)(Qs + row * 144 + c + 16) = *(const float4*)(src + 8);
    }
    // ---- load K (256 rows x 128B) ----
    #pragma unroll
    for (int rp = 0; rp < 4; rp++) {
        int row = (tid >> 2) + rp * 64, c = (tid & 3) * 32;
        const __half* src = Kg + (size_t)row * DD + (c >> 1);
        *(float4*)(KV + row * 144 + c)      = *(const float4*)(src);
        *(float4*)(KV + row * 144 + c + 16) = *(const float4*)(src + 8);
    }
    __syncthreads();

    const int wm = wid & 3, wn = wid >> 2;
    const uint32_t sbQ = smem_u32(Qs);
    const uint32_t sbK = smem_u32(KV);
    const uint32_t sbP = smem_u32(Ph);

    // ---- Phase 1: scores (rows wm*16..+15, cols wn*128..+127) ----
    float acc[16][4];
    #pragma unroll
    for (int j = 0; j < 16; j++)
        #pragma unroll
        for (int p = 0; p < 4; p++) acc[j][p] = 0.0f;

    {
        uint32_t qa[4][4];
        const uint32_t qoff = sbQ + (wm * 16 + ((quad & 1) << 3) + li) * 144
                              + ((quad >> 1) << 4);
        #pragma unroll
        for (int ks = 0; ks < 4; ks++) ldsm_x4(qa[ks], qoff + ks * 32);

        const uint32_t koff = sbK + (((quad & 2) ? 8 : 0) + li) * 144 + ((quad & 1) << 4);
        #pragma unroll
        for (int j2 = 0; j2 < 8; j2++) {
            #pragma unroll
            for (int ks = 0; ks < 4; ks++) {
                uint32_t bf[4];
                ldsm_x4(bf, koff + (wn * 128 + j2 * 16) * 144 + ks * 32);
                mma_f16(acc[2 * j2],     qa[ks], bf);
                mma_f16(acc[2 * j2 + 1], qa[ks], bf + 2);
            }
        }
    }

    // ---- mask + scale + softmax (fp32 in regs) ----
    {
        const int row_lo = qb * 64 + wm * 16 + r;
        const int row_hi = row_lo + 8;
        float mlo = -1e30f, mhi = -1e30f;
        #pragma unroll
        for (int j = 0; j < 16; j++) {
            int gc = wn * 128 + j * 8 + cf * 2;
            bool ok0 = ids_s[gc] > 0, ok1 = ids_s[gc + 1] > 0;
            acc[j][0] = acc[j][0] * 0.125f + ((ok0 && gc     <= row_lo) ? 0.0f : -10000.0f);
            acc[j][1] = acc[j][1] * 0.125f + ((ok1 && gc + 1 <= row_lo) ? 0.0f : -10000.0f);
            acc[j][2] = acc[j][2] * 0.125f + ((ok0 && gc     <= row_hi) ? 0.0f : -10000.0f);
            acc[j][3] = acc[j][3] * 0.125f + ((ok1 && gc + 1 <= row_hi) ? 0.0f : -10000.0f);
            mlo = fmaxf(mlo, fmaxf(acc[j][0], acc[j][1]));
            mhi = fmaxf(mhi, fmaxf(acc[j][2], acc[j][3]));
        }
        mlo = fmaxf(mlo, __shfl_xor_sync(0xFFFFFFFFu, mlo, 1));
        mlo = fmaxf(mlo, __shfl_xor_sync(0xFFFFFFFFu, mlo, 2));
        mhi = fmaxf(mhi, __shfl_xor_sync(0xFFFFFFFFu, mhi, 1));
        mhi = fmaxf(mhi, __shfl_xor_sync(0xFFFFFFFFu, mhi, 2));
        if (cf == 0) {
            red[(wm * 16 + r) * 2 + wn]     = mlo;
            red[(wm * 16 + 8 + r) * 2 + wn] = mhi;
        }
        __syncthreads();
        float Mlo = fmaxf(red[(wm * 16 + r) * 2],     red[(wm * 16 + r) * 2 + 1]);
        float Mhi = fmaxf(red[(wm * 16 + 8 + r) * 2], red[(wm * 16 + 8 + r) * 2 + 1]);

        float slo = 0.0f, shi = 0.0f;
        #pragma unroll
        for (int j = 0; j < 16; j++) {
            acc[j][0] = __expf(acc[j][0] - Mlo);
            acc[j][1] = __expf(acc[j][1] - Mlo);
            acc[j][2] = __expf(acc[j][2] - Mhi);
            acc[j][3] = __expf(acc[j][3] - Mhi);
            slo += acc[j][0] + acc[j][1];
            shi += acc[j][2] + acc[j][3];
        }
        slo += __shfl_xor_sync(0xFFFFFFFFu, slo, 1);
        slo += __shfl_xor_sync(0xFFFFFFFFu, slo, 2);
        shi += __shfl_xor_sync(0xFFFFFFFFu, shi, 1);
        shi += __shfl_xor_sync(0xFFFFFFFFu, shi, 2);
        if (cf == 0) {
            red[128 + (wm * 16 + r) * 2 + wn]     = slo;
            red[128 + (wm * 16 + 8 + r) * 2 + wn] = shi;
        }
        __syncthreads();
        float inv_lo = 1.0f / (red[128 + (wm * 16 + r) * 2]     + red[128 + (wm * 16 + r) * 2 + 1]);
        float inv_hi = 1.0f / (red[128 + (wm * 16 + 8 + r) * 2] + red[128 + (wm * 16 + 8 + r) * 2 + 1]);

        #pragma unroll
        for (int j = 0; j < 16; j++) {
            int gc = wn * 128 + j * 8 + cf * 2;
            *(__half2*)(Ph + (wm * 16 + r) * 528 + gc * 2) =
                __floats2half2_rn(acc[j][0] * inv_lo, acc[j][1] * inv_lo);
            *(__half2*)(Ph + (wm * 16 + 8 + r) * 528 + gc * 2) =
                __floats2half2_rn(acc[j][2] * inv_hi, acc[j][3] * inv_hi);
        }
    }
    __syncthreads();

    // ---- load V (overwrites K buffer) ----
    #pragma unroll
    for (int rp = 0; rp < 4; rp++) {
        int row = (tid >> 2) + rp * 64, c = (tid & 3) * 32;
        const __half* src = Vg + (size_t)row * DD + (c >> 1);
        *(float4*)(KV + row * 144 + c)      = *(const float4*)(src);
        *(float4*)(KV + row * 144 + c + 16) = *(const float4*)(src + 8);
    }
    __syncthreads();

    // ---- Phase PV: rows wm*16..+15, cols wn*32..+31, k=256 ----
    {
        float acc2[4][4];
        #pragma unroll
        for (int j = 0; j < 4; j++)
            #pragma unroll
            for (int p = 0; p < 4; p++) acc2[j][p] = 0.0f;

        const uint32_t poff = sbP + (wm * 16 + ((quad & 1) << 3) + li) * 528
                              + ((quad >> 1) << 4);
        const int vrow_l = ((quad & 1) << 3) + li;
        const int vcol_l = ((quad >> 1) << 3);

        #pragma unroll 4
        for (int ks = 0; ks < 16; ks++) {
            uint32_t pa[4];
            ldsm_x4(pa, poff + ks * 32);
            #pragma unroll
            for (int j2 = 0; j2 < 2; j2++) {
                uint32_t vb[4];
                ldsm_x4_t(vb, sbK + (ks * 16 + vrow_l) * 144
                              + (wn * 32 + j2 * 16 + vcol_l) * 2);
                mma_f16(acc2[2 * j2],     pa, vb);
                mma_f16(acc2[2 * j2 + 1], pa, vb + 2);
            }
        }

        #pragma unroll
        for (int j = 0; j < 4; j++) {
            int lrow = wm * 16 + r;
            int gc   = wn * 32 + j * 8 + cf * 2;
            *(__half2*)(Cg + (size_t)lrow * DD + gc) =
                __floats2half2_rn(acc2[j][0], acc2[j][1]);
            *(__half2*)(Cg + (size_t)(lrow + 8) * DD + gc) =
                __floats2half2_rn(acc2[j][2], acc2[j][3]);
        }
    }
}

// ---------------- host orchestration ----------------
extern "C" void kernel_launch(void* const* d_in, const int* in_sizes, int n_in,
                              void* d_out, int out_size) {
    const int*   ids      = (const int*)  d_in[0];
    const float* item_emb = (const float*)d_in[1];
    const float* pos_emb  = (const float*)d_in[2];
    const float* Wq = (const float*)d_in[3];
    const float* bq = (const float*)d_in[4];
    const float* Wk = (const float*)d_in[5];
    const float* bk = (const float*)d_in[6];
    const float* Wv = (const float*)d_in[7];
    const float* bv = (const float*)d_in[8];
    const float* Wo = (const float*)d_in[9];
    const float* bo = (const float*)d_in[10];
    const float* W1 = (const float*)d_in[11];
    const float* b1 = (const float*)d_in[12];
    const float* W2 = (const float*)d_in[13];
    const float* b2 = (const float*)d_in[14];
    float* out = (float*)d_out;

    float *x, *tmp;
    __half *xt, *q, *k, *v, *ctxt, *ht, *midt, *wt;
    cudaGetSymbolAddress((void**)&x,    g_x);
    cudaGetSymbolAddress((void**)&tmp,  g_tmp);
    cudaGetSymbolAddress((void**)&xt,   g_xt);
    cudaGetSymbolAddress((void**)&q,    g_q);
    cudaGetSymbolAddress((void**)&k,    g_k);
    cudaGetSymbolAddress((void**)&v,    g_v);
    cudaGetSymbolAddress((void**)&ctxt, g_ctxt);
    cudaGetSymbolAddress((void**)&ht,   g_ht);
    cudaGetSymbolAddress((void**)&midt, g_midt);
    cudaGetSymbolAddress((void**)&wt,   g_wt);

    cudaFuncSetAttribute(attn_fused, cudaFuncAttributeMaxDynamicSharedMemorySize,
                         ATTN_SMEM_BYTES);
    cudaFuncSetAttribute(hgemm<1,0,0>, cudaFuncAttributeMaxDynamicSharedMemorySize, HGEMM_SMEM);
    cudaFuncSetAttribute(hgemm<0,0,1>, cudaFuncAttributeMaxDynamicSharedMemorySize, HGEMM_SMEM);
    cudaFuncSetAttribute(hgemm<1,1,0>, cudaFuncAttributeMaxDynamicSharedMemorySize, HGEMM_SMEM);
    cudaFuncSetAttribute(hgemm<0,0,0>, cudaFuncAttributeMaxDynamicSharedMemorySize, HGEMM_SMEM);

    // ---- convert weights ----
    const int gDDxDD = (DD * DD + 255) / 256;
    const int gDDxFF = (DD * FF + 255) / 256;
    for (int l = 0; l < LL; l++) {
        __half* base = wt + (size_t)l * 786432;
        conv_weight<<<gDDxDD, 256>>>(Wq + (size_t)l * DD * DD, base,          DD, DD);
        conv_weight<<<gDDxDD, 256>>>(Wk + (size_t)l * DD * DD, base + 65536,  DD, DD);
        conv_weight<<<gDDxDD, 256>>>(Wv + (size_t)l * DD * DD, base + 131072, DD, DD);
        conv_weight<<<gDDxDD, 256>>>(Wo + (size_t)l * DD * DD, base + 196608, DD, DD);
        conv_weight<<<gDDxFF, 256>>>(W1 + (size_t)l * DD * FF, base + 262144, DD, FF);
        conv_weight<<<gDDxFF, 256>>>(W2 + (size_t)l * FF * DD, base + 524288, FF, DD);
    }

    embed_ln_kernel<<<MM, 256>>>(ids, item_emb, pos_emb, x, xt, out);

    dim3 gProj(DD / 128, MM / 128);     // (2, 512)
    dim3 gFF1(FF / 128, MM / 128);      // (8, 512)
    dim3 gAttn(SS / 64, BB * HH);       // (4, 1024)

    for (int l = 0; l < LL; l++) {
        __half* base = wt + (size_t)l * 786432;
        const __half* Wqt = base;
        const __half* Wkt = base + 65536;
        const __half* Wvt = base + 131072;
        const __half* Wot = base + 196608;
        const __half* W1t = base + 262144;
        const __half* W2t = base + 524288;
        const float* bql = bq + l * DD;
        const float* bkl = bk + l * DD;
        const float* bvl = bv + l * DD;
        const float* bol = bo + l * DD;
        const float* b1l = b1 + l * FF;
        const float* b2l = b2 + l * DD;

        hgemm<1,0,0><<<gProj, 256, HGEMM_SMEM>>>(xt, Wqt, bql, nullptr, q, DD, DD);
        hgemm<1,0,0><<<gProj, 256, HGEMM_SMEM>>>(xt, Wkt, bkl, nullptr, k, DD, DD);
        hgemm<1,0,0><<<gProj, 256, HGEMM_SMEM>>>(xt, Wvt, bvl, nullptr, v, DD, DD);

        attn_fused<<<gAttn, 256, ATTN_SMEM_BYTES>>>(q, k, v, ids, ctxt);

        hgemm<0,0,1><<<gProj, 256, HGEMM_SMEM>>>(ctxt, Wot, bol, x, tmp, DD, DD);
        ln_kernel<<<MM, 256>>>(tmp, ht);

        hgemm<1,1,0><<<gFF1, 256, HGEMM_SMEM>>>(ht, W1t, b1l, nullptr, midt, DD, FF);
        hgemm<0,0,0><<<gProj, 256, HGEMM_SMEM>>>(midt, W2t, b2l, nullptr, tmp, FF, DD);
        ln_accum_kernel<<<MM, 256>>>(tmp, x, xt, out);
    }
}

// round 9
// speedup vs baseline: 5.0518x; 1.2298x over previous
#include <cuda_runtime.h>
#include <cuda_fp16.h>
#include <math.h>
#include <stdint.h>

#define BB 256
#define SS 256
#define DD 256
#define HH 4
#define DHH 64
#define LL 2
#define MM (BB*SS)          // 65536
#define FF (4*DD)           // 1024
#define QKVN 768

// ---------------- scratch (no malloc allowed) ----------------
__device__ float g_x  [ (size_t)MM*DD ];                     // fp32 residual
__device__ __align__(16) __half g_xt  [ (size_t)MM*DD ];     // half activations
__device__ __align__(16) __half g_qkv [ (size_t)MM*QKVN ];   // packed q|k|v
__device__ __align__(16) __half g_ctxt[ (size_t)MM*DD ];
__device__ __align__(16) __half g_ht  [ (size_t)MM*DD ];
__device__ __align__(16) __half g_midt[ (size_t)MM*FF ];
__device__ __align__(16) __half g_wt  [ (size_t)LL*786432 ]; // converted weights
__device__ float g_bqkv [ (size_t)LL*QKVN ];                 // concat qkv bias

// ---------------- helpers ----------------
__device__ __forceinline__ float block_sum_256(float v, float* sh) {
    int tid = threadIdx.x;
    sh[tid] = v; __syncthreads();
    #pragma unroll
    for (int s = 128; s > 0; s >>= 1) {
        if (tid < s) sh[tid] += sh[tid + s];
        __syncthreads();
    }
    float r = sh[0];
    __syncthreads();
    return r;
}

__device__ __forceinline__ void mma_f16(float* d, const uint32_t* a, const uint32_t* b) {
    asm volatile("mma.sync.aligned.m16n8k16.row.col.f32.f16.f16.f32 "
        "{%0,%1,%2,%3}, {%4,%5,%6,%7}, {%8,%9}, {%0,%1,%2,%3};"
        : "+f"(d[0]), "+f"(d[1]), "+f"(d[2]), "+f"(d[3])
        : "r"(a[0]), "r"(a[1]), "r"(a[2]), "r"(a[3]), "r"(b[0]), "r"(b[1]));
}

__device__ __forceinline__ void ldsm_x4(uint32_t* d, uint32_t a) {
    asm volatile("ldmatrix.sync.aligned.m8n8.x4.shared.b16 {%0,%1,%2,%3}, [%4];"
        : "=r"(d[0]), "=r"(d[1]), "=r"(d[2]), "=r"(d[3]) : "r"(a));
}
__device__ __forceinline__ void ldsm_x4_t(uint32_t* d, uint32_t a) {
    asm volatile("ldmatrix.sync.aligned.m8n8.x4.trans.shared.b16 {%0,%1,%2,%3}, [%4];"
        : "=r"(d[0]), "=r"(d[1]), "=r"(d[2]), "=r"(d[3]) : "r"(a));
}

__device__ __forceinline__ void cp_async16(uint32_t s, const void* g) {
    asm volatile("cp.async.cg.shared.global [%0], [%1], 16;" :: "r"(s), "l"(g));
}
__device__ __forceinline__ void cp_commit() { asm volatile("cp.async.commit_group;"); }
template<int N_> __device__ __forceinline__ void cp_wait() {
    asm volatile("cp.async.wait_group %0;" :: "n"(N_));
}

__device__ __forceinline__ uint32_t smem_u32(const void* p) {
    uint32_t a;
    asm("{ .reg .u64 t; cvta.to.shared.u64 t, %1; cvt.u32.u64 %0, t; }" : "=r"(a) : "l"(p));
    return a;
}

// ---------------- batched weight convert (all layers, one launch) ----------------
// wt layout per layer (stride 786432):
//   [0,196608)      qkv  [768][256]   (rows: 0-255 Wq, 256-511 Wk, 512-767 Wv)
//   [196608,262144) Wo   [256][256]
//   [262144,524288) W1   [1024][256]
//   [524288,786432) W2   [256][1024]
__global__ void conv_all(const float* __restrict__ Wq, const float* __restrict__ Wk,
                         const float* __restrict__ Wv, const float* __restrict__ Wo,
                         const float* __restrict__ W1, const float* __restrict__ W2,
                         __half* __restrict__ wt) {
    size_t idx = (size_t)blockIdx.x * 256 + threadIdx.x;
    if (idx >= (size_t)LL * 786432) return;
    int l = (int)(idx / 786432);
    int off = (int)(idx % 786432);
    const float* src; int N, K, local;
    if (off < 196608) {
        int w = off >> 16; local = off & 65535; K = 256; N = 256;
        src = (w == 0 ? Wq : (w == 1 ? Wk : Wv)) + (size_t)l * 65536;
    } else if (off < 262144) {
        local = off - 196608; K = 256; N = 256; src = Wo + (size_t)l * 65536;
    } else if (off < 524288) {
        local = off - 262144; K = 256; N = 1024; src = W1 + (size_t)l * 262144;
    } else {
        local = off - 524288; K = 1024; N = 256; src = W2 + (size_t)l * 262144;
    }
    int n = local / K, k = local % K;
    wt[idx] = __float2half_rn(src[(size_t)k * N + n]);
}

__global__ void concat_bias(const float* __restrict__ bq, const float* __restrict__ bk,
                            const float* __restrict__ bv, float* __restrict__ dst) {
    int l = blockIdx.y;
    int i = blockIdx.x * 256 + threadIdx.x;   // 0..767
    float v = (i < 256) ? bq[l * 256 + i]
            : (i < 512) ? bk[l * 256 + i - 256]
                        : bv[l * 256 + i - 512];
    dst[l * QKVN + i] = v;
}

// ---------------- embedding + LN ----------------
__global__ void embed_ln_kernel(const int* __restrict__ ids,
                                const float* __restrict__ item_emb,
                                const float* __restrict__ pos_emb,
                                float* __restrict__ x, __half* __restrict__ xt,
                                float* __restrict__ out) {
    __shared__ float sh[256];
    int row = blockIdx.x;
    int s   = row & (SS - 1);
    int tid = threadIdx.x;
    int id  = ids[row];
    float v = item_emb[(size_t)id * DD + tid] + pos_emb[s * DD + tid];
    float mu  = block_sum_256(v, sh) * (1.0f / DD);
    float d   = v - mu;
    float var = block_sum_256(d * d, sh) * (1.0f / DD);
    float o   = d * rsqrtf(var + 1e-5f);
    size_t idx = (size_t)row * DD + tid;
    x[idx] = o;
    out[idx] = o;
    xt[idx] = __float2half_rn(o);
}

// =====================================================================
// FP16 GEMM (128x128 tile, BK=32, 3-stage cp.async, 8 warps).
// Used for QKV (N=768) and FF1 (N=1024). OUTHALF output; optional GELU.
// =====================================================================
#define HGEMM_SMEM (3 * 20480)

template<int GELU>
__global__ void __launch_bounds__(256, 2)
hgemm(const __half* __restrict__ A, const __half* __restrict__ Bt,
      const float* __restrict__ bias, __half* __restrict__ C, int K, int N)
{
    extern __shared__ char smem[];
    const uint32_t sb = smem_u32(smem);

    const int tid  = threadIdx.x;
    const int lane = tid & 31;
    const int wid  = tid >> 5;
    const int warp_m = wid & 1;
    const int warp_n = wid >> 1;
    const int r  = lane >> 2;
    const int cf = lane & 3;
    const int quad = lane >> 3, li = lane & 7;

    const int bm = blockIdx.y << 7;
    const int bn = blockIdx.x << 7;

    const int lrow = tid >> 1;
    const int lc   = (tid & 1) * 32;
    const __half* Ag = A  + (size_t)(bm + lrow) * K + (lc >> 1);
    const __half* Bg = Bt + (size_t)(bn + lrow) * K + (lc >> 1);
    const uint32_t sA = sb +         lrow * 80 + lc;
    const uint32_t sB = sb + 10240 + lrow * 80 + lc;

    const int nsteps = K >> 5;

    #pragma unroll
    for (int s = 0; s < 2; s++) {
        cp_async16(sA + s * 20480,      Ag + s * 32);
        cp_async16(sA + s * 20480 + 16, Ag + s * 32 + 8);
        cp_async16(sB + s * 20480,      Bg + s * 32);
        cp_async16(sB + s * 20480 + 16, Bg + s * 32 + 8);
        cp_commit();
    }

    const uint32_t aoff = (uint32_t)((warp_m * 64 + ((quad & 1) << 3) + li) * 80
                                     + ((quad >> 1) << 4));
    const uint32_t boff = (uint32_t)(10240 + (warp_n * 32 + ((quad & 2) ? 8 : 0) + li) * 80
                                     + ((quad & 1) << 4));

    float acc[4][4][4];
    #pragma unroll
    for (int i = 0; i < 4; i++)
        #pragma unroll
        for (int j = 0; j < 4; j++)
            #pragma unroll
            for (int p = 0; p < 4; p++) acc[i][j][p] = 0.0f;

    for (int s = 0; s < nsteps; s++) {
        if (s + 1 < nsteps) cp_wait<1>(); else cp_wait<0>();
        __syncthreads();
        if (s + 2 < nsteps) {
            const uint32_t st = ((s + 2) % 3) * 20480;
            cp_async16(sA + st,      Ag + (s + 2) * 32);
            cp_async16(sA + st + 16, Ag + (s + 2) * 32 + 8);
            cp_async16(sB + st,      Bg + (s + 2) * 32);
            cp_async16(sB + st + 16, Bg + (s + 2) * 32 + 8);
            cp_commit();
        }
        const uint32_t stg = sb + (s % 3) * 20480;

        uint32_t af[2][4][4];
        #pragma unroll
        for (int ks = 0; ks < 2; ks++)
            #pragma unroll
            for (int i = 0; i < 4; i++)
                ldsm_x4(af[ks][i], stg + aoff + i * 1280 + ks * 32);

        #pragma unroll
        for (int ks = 0; ks < 2; ks++) {
            #pragma unroll
            for (int j2 = 0; j2 < 2; j2++) {
                uint32_t bf[4];
                ldsm_x4(bf, stg + boff + j2 * 1280 + ks * 32);
                #pragma unroll
                for (int i = 0; i < 4; i++) {
                    mma_f16(acc[i][2 * j2],     af[ks][i], bf);
                    mma_f16(acc[i][2 * j2 + 1], af[ks][i], bf + 2);
                }
            }
        }
    }

    #pragma unroll
    for (int i = 0; i < 4; i++) {
        #pragma unroll
        for (int j = 0; j < 4; j++) {
            int gr0 = bm + warp_m * 64 + i * 16 + r;
            int gc  = bn + warp_n * 32 + j * 8 + cf * 2;
            float v00 = acc[i][j][0] + bias[gc];
            float v01 = acc[i][j][1] + bias[gc + 1];
            float v10 = acc[i][j][2] + bias[gc];
            float v11 = acc[i][j][3] + bias[gc + 1];
            if (GELU) {
                v00 = 0.5f * v00 * (1.0f + erff(v00 * 0.7071067811865476f));
                v01 = 0.5f * v01 * (1.0f + erff(v01 * 0.7071067811865476f));
                v10 = 0.5f * v10 * (1.0f + erff(v10 * 0.7071067811865476f));
                v11 = 0.5f * v11 * (1.0f + erff(v11 * 0.7071067811865476f));
            }
            *(__half2*)(C + (size_t)gr0 * N + gc)       = __floats2half2_rn(v00, v01);
            *(__half2*)(C + (size_t)(gr0 + 8) * N + gc) = __floats2half2_rn(v10, v11);
        }
    }
}

// =====================================================================
// FP16 GEMM with fused LayerNorm epilogue. Tile 128x256 (full row, N=256),
// 512 threads = 16 warps (warp_m = wid&1, warp_n = wid>>1 in 0..7).
// MODE 1 (Wo):  ht = LN(A@W + bias + resid)            -> Ch (half)
// MODE 2 (FF2): o = LN(A@W + bias); x=o; total+=o; xt=half(o)
// smem: 3 stages x (A 10240 + B 20480) = 92160 B; LN partials alias stage 0.
// =====================================================================
#define HGEMM_LN_SMEM (3 * 30720)

template<int MODE>
__global__ void __launch_bounds__(512, 1)
hgemm_ln(const __half* __restrict__ A, const __half* __restrict__ Bt,
         const float* __restrict__ bias, const float* __restrict__ resid,
         __half* __restrict__ Ch, float* __restrict__ x,
         __half* __restrict__ xt, float* __restrict__ total, int K)
{
    extern __shared__ char smem[];
    const uint32_t sb = smem_u32(smem);
    const int N = 256;

    const int tid  = threadIdx.x;
    const int lane = tid & 31;
    const int wid  = tid >> 5;
    const int warp_m = wid & 1;
    const int warp_n = wid >> 1;           // 0..7
    const int r  = lane >> 2;
    const int cf = lane & 3;
    const int quad = lane >> 3, li = lane & 7;

    const int bm = blockIdx.x << 7;

    // loaders: A 128x64B (512 chunks, 1/thread); B 256x64B (1024 chunks, 2/thread)
    const int arow = tid >> 2;
    const int ac   = (tid & 3) * 16;       // byte offset
    const __half* Ag = A + (size_t)(bm + arow) * K + (ac >> 1);
    const uint32_t sA = sb + arow * 80 + ac;

    const int brow0 = tid >> 2;            // chunk c = tid  -> rows 0..127
    const int brow1 = (tid + 512) >> 2;    // chunk c2       -> rows 128..255
    const __half* Bg0 = Bt + (size_t)brow0 * K + (ac >> 1);
    const __half* Bg1 = Bt + (size_t)brow1 * K + (ac >> 1);
    const uint32_t sB0 = sb + 10240 + brow0 * 80 + ac;
    const uint32_t sB1 = sb + 10240 + brow1 * 80 + ac;

    const int nsteps = K >> 5;

    #pragma unroll
    for (int s = 0; s < 2; s++) {
        cp_async16(sA  + s * 30720, Ag  + s * 32);
        cp_async16(sB0 + s * 30720, Bg0 + s * 32);
        cp_async16(sB1 + s * 30720, Bg1 + s * 32);
        cp_commit();
    }

    const uint32_t aoff = (uint32_t)((warp_m * 64 + ((quad & 1) << 3) + li) * 80
                                     + ((quad >> 1) << 4));
    const uint32_t boff = (uint32_t)(10240 + (warp_n * 32 + ((quad & 2) ? 8 : 0) + li) * 80
                                     + ((quad & 1) << 4));

    float acc[4][4][4];
    #pragma unroll
    for (int i = 0; i < 4; i++)
        #pragma unroll
        for (int j = 0; j < 4; j++)
            #pragma unroll
            for (int p = 0; p < 4; p++) acc[i][j][p] = 0.0f;

    for (int s = 0; s < nsteps; s++) {
        if (s + 1 < nsteps) cp_wait<1>(); else cp_wait<0>();
        __syncthreads();
        if (s + 2 < nsteps) {
            const uint32_t st = ((s + 2) % 3) * 30720;
            cp_async16(sA  + st, Ag  + (s + 2) * 32);
            cp_async16(sB0 + st, Bg0 + (s + 2) * 32);
            cp_async16(sB1 + st, Bg1 + (s + 2) * 32);
            cp_commit();
        }
        const uint32_t stg = sb + (s % 3) * 30720;

        uint32_t af[2][4][4];
        #pragma unroll
        for (int ks = 0; ks < 2; ks++)
            #pragma unroll
            for (int i = 0; i < 4; i++)
                ldsm_x4(af[ks][i], stg + aoff + i * 1280 + ks * 32);

        #pragma unroll
        for (int ks = 0; ks < 2; ks++) {
            #pragma unroll
            for (int j2 = 0; j2 < 2; j2++) {
                uint32_t bf[4];
                ldsm_x4(bf, stg + boff + j2 * 1280 + ks * 32);
                #pragma unroll
                for (int i = 0; i < 4; i++) {
                    mma_f16(acc[i][2 * j2],     af[ks][i], bf);
                    mma_f16(acc[i][2 * j2 + 1], af[ks][i], bf + 2);
                }
            }
        }
    }
    __syncthreads();   // all MMA smem reads done -> safe to alias LN buffers

    // ---- bias (+resid) into acc ----
    #pragma unroll
    for (int i = 0; i < 4; i++) {
        int gr0 = bm + warp_m * 64 + i * 16 + r;
        #pragma unroll
        for (int j = 0; j < 4; j++) {
            int gc = warp_n * 32 + j * 8 + cf * 2;
            float b0 = bias[gc], b1 = bias[gc + 1];
            acc[i][j][0] += b0; acc[i][j][1] += b1;
            acc[i][j][2] += b0; acc[i][j][3] += b1;
            if (MODE == 1) {
                acc[i][j][0] += resid[(size_t)gr0 * N + gc];
                acc[i][j][1] += resid[(size_t)gr0 * N + gc + 1];
                acc[i][j][2] += resid[(size_t)(gr0 + 8) * N + gc];
                acc[i][j][3] += resid[(size_t)(gr0 + 8) * N + gc + 1];
            }
        }
    }

    // ---- LN pass 1: mean ----
    float* redA = (float*)smem;            // [128][8]
    float* redB = (float*)(smem + 4096);   // [128][8]
    #pragma unroll
    for (int i = 0; i < 4; i++) {
        float s_lo = 0.0f, s_hi = 0.0f;
        #pragma unroll
        for (int j = 0; j < 4; j++) {
            s_lo += acc[i][j][0] + acc[i][j][1];
            s_hi += acc[i][j][2] + acc[i][j][3];
        }
        s_lo += __shfl_xor_sync(0xFFFFFFFFu, s_lo, 1);
        s_lo += __shfl_xor_sync(0xFFFFFFFFu, s_lo, 2);
        s_hi += __shfl_xor_sync(0xFFFFFFFFu, s_hi, 1);
        s_hi += __shfl_xor_sync(0xFFFFFFFFu, s_hi, 2);
        if (cf == 0) {
            int rl = warp_m * 64 + i * 16 + r;
            redA[rl * 8 + warp_n]       = s_lo;
            redA[(rl + 8) * 8 + warp_n] = s_hi;
        }
    }
    __syncthreads();
    float mu[4][2];
    #pragma unroll
    for (int i = 0; i < 4; i++) {
        int rl = warp_m * 64 + i * 16 + r;
        float a = 0.0f, b = 0.0f;
        #pragma unroll
        for (int w = 0; w < 8; w++) { a += redA[rl * 8 + w]; b += redA[(rl + 8) * 8 + w]; }
        mu[i][0] = a * (1.0f / 256.0f);
        mu[i][1] = b * (1.0f / 256.0f);
    }

    // ---- LN pass 2: variance ----
    #pragma unroll
    for (int i = 0; i < 4; i++) {
        float s_lo = 0.0f, s_hi = 0.0f;
        #pragma unroll
        for (int j = 0; j < 4; j++) {
            float d0 = acc[i][j][0] - mu[i][0], d1 = acc[i][j][1] - mu[i][0];
            float d2 = acc[i][j][2] - mu[i][1], d3 = acc[i][j][3] - mu[i][1];
            s_lo += d0 * d0 + d1 * d1;
            s_hi += d2 * d2 + d3 * d3;
        }
        s_lo += __shfl_xor_sync(0xFFFFFFFFu, s_lo, 1);
        s_lo += __shfl_xor_sync(0xFFFFFFFFu, s_lo, 2);
        s_hi += __shfl_xor_sync(0xFFFFFFFFu, s_hi, 1);
        s_hi += __shfl_xor_sync(0xFFFFFFFFu, s_hi, 2);
        if (cf == 0) {
            int rl = warp_m * 64 + i * 16 + r;
            redB[rl * 8 + warp_n]       = s_lo;
            redB[(rl + 8) * 8 + warp_n] = s_hi;
        }
    }
    __syncthreads();

    #pragma unroll
    for (int i = 0; i < 4; i++) {
        int rl = warp_m * 64 + i * 16 + r;
        float a = 0.0f, b = 0.0f;
        #pragma unroll
        for (int w = 0; w < 8; w++) { a += redB[rl * 8 + w]; b += redB[(rl + 8) * 8 + w]; }
        float rs_lo = rsqrtf(a * (1.0f / 256.0f) + 1e-5f);
        float rs_hi = rsqrtf(b * (1.0f / 256.0f) + 1e-5f);
        int gr0 = bm + rl;
        #pragma unroll
        for (int j = 0; j < 4; j++) {
            int gc = warp_n * 32 + j * 8 + cf * 2;
            float o00 = (acc[i][j][0] - mu[i][0]) * rs_lo;
            float o01 = (acc[i][j][1] - mu[i][0]) * rs_lo;
            float o10 = (acc[i][j][2] - mu[i][1]) * rs_hi;
            float o11 = (acc[i][j][3] - mu[i][1]) * rs_hi;
            if (MODE == 1) {
                *(__half2*)(Ch + (size_t)gr0 * N + gc)       = __floats2half2_rn(o00, o01);
                *(__half2*)(Ch + (size_t)(gr0 + 8) * N + gc) = __floats2half2_rn(o10, o11);
            } else {
                size_t i0 = (size_t)gr0 * N + gc;
                size_t i1 = (size_t)(gr0 + 8) * N + gc;
                *(float2*)(x + i0) = make_float2(o00, o01);
                *(float2*)(x + i1) = make_float2(o10, o11);
                float2 t0 = *(float2*)(total + i0);
                float2 t1 = *(float2*)(total + i1);
                t0.x += o00; t0.y += o01; t1.x += o10; t1.y += o11;
                *(float2*)(total + i0) = t0;
                *(float2*)(total + i1) = t1;
                *(__half2*)(xt + i0) = __floats2half2_rn(o00, o01);
                *(__half2*)(xt + i1) = __floats2half2_rn(o10, o11);
            }
        }
    }
}

// =====================================================================
// Fused FP16 attention reading packed qkv [M][768].
// =====================================================================
#define ATTN_SMEM_BYTES 81920

__global__ void __launch_bounds__(256, 2)
attn_fused(const __half* __restrict__ qkv, const int* __restrict__ ids,
           __half* __restrict__ ctxt)
{
    extern __shared__ char sm[];
    char* Qs = sm;                    // 9216 B
    char* KV = sm + 9216;             // 36864 B
    char* Ph = sm + 46080;            // 33792 B
    float* red   = (float*)(sm + 79872);   // [2][64][2]
    int*   ids_s = (int*)(sm + 80896);

    const int tid  = threadIdx.x;
    const int lane = tid & 31;
    const int wid  = tid >> 5;
    const int r  = lane >> 2;
    const int cf = lane & 3;
    const int quad = lane >> 3, li = lane & 7;

    const int qb = blockIdx.x;
    const int bh = blockIdx.y;
    const int b  = bh >> 2, h = bh & 3;

    const __half* Qg = qkv + ((size_t)b * SS + qb * 64) * QKVN + h * DHH;
    const __half* Kg = qkv + (size_t)b * SS * QKVN + 256 + h * DHH;
    const __half* Vg = qkv + (size_t)b * SS * QKVN + 512 + h * DHH;
    __half* Cg = ctxt + (size_t)b * SS * DD + h * DHH + (size_t)qb * 64 * DD;
    const int* idb = ids + b * SS;

    ids_s[tid] = idb[tid];

    {
        int row = tid >> 2, c = (tid & 3) * 32;
        const __half* src = Qg + (size_t)row * QKVN + (c >> 1);
        *(float4*)(Qs + row * 144 + c)      = *(const float4*)(src);
        *(float4*)(Qs + row * 144 + c + 16) = *(const float4*)(src + 8);
    }
    #pragma unroll
    for (int rp = 0; rp < 4; rp++) {
        int row = (tid >> 2) + rp * 64, c = (tid & 3) * 32;
        const __half* src = Kg + (size_t)row * QKVN + (c >> 1);
        *(float4*)(KV + row * 144 + c)      = *(const float4*)(src);
        *(float4*)(KV + row * 144 + c + 16) = *(const float4*)(src + 8);
    }
    __syncthreads();

    const int wm = wid & 3, wn = wid >> 2;
    const uint32_t sbQ = smem_u32(Qs);
    const uint32_t sbK = smem_u32(KV);
    const uint32_t sbP = smem_u32(Ph);

    float acc[16][4];
    #pragma unroll
    for (int j = 0; j < 16; j++)
        #pragma unroll
        for (int p = 0; p < 4; p++) acc[j][p] = 0.0f;

    {
        uint32_t qa[4][4];
        const uint32_t qoff = sbQ + (wm * 16 + ((quad & 1) << 3) + li) * 144
                              + ((quad >> 1) << 4);
        #pragma unroll
        for (int ks = 0; ks < 4; ks++) ldsm_x4(qa[ks], qoff + ks * 32);

        const uint32_t koff = sbK + (((quad & 2) ? 8 : 0) + li) * 144 + ((quad & 1) << 4);
        #pragma unroll
        for (int j2 = 0; j2 < 8; j2++) {
            #pragma unroll
            for (int ks = 0; ks < 4; ks++) {
                uint32_t bf[4];
                ldsm_x4(bf, koff + (wn * 128 + j2 * 16) * 144 + ks * 32);
                mma_f16(acc[2 * j2],     qa[ks], bf);
                mma_f16(acc[2 * j2 + 1], qa[ks], bf + 2);
            }
        }
    }

    {
        const int row_lo = qb * 64 + wm * 16 + r;
        const int row_hi = row_lo + 8;
        float mlo = -1e30f, mhi = -1e30f;
        #pragma unroll
        for (int j = 0; j < 16; j++) {
            int gc = wn * 128 + j * 8 + cf * 2;
            bool ok0 = ids_s[gc] > 0, ok1 = ids_s[gc + 1] > 0;
            acc[j][0] = acc[j][0] * 0.125f + ((ok0 && gc     <= row_lo) ? 0.0f : -10000.0f);
            acc[j][1] = acc[j][1] * 0.125f + ((ok1 && gc + 1 <= row_lo) ? 0.0f : -10000.0f);
            acc[j][2] = acc[j][2] * 0.125f + ((ok0 && gc     <= row_hi) ? 0.0f : -10000.0f);
            acc[j][3] = acc[j][3] * 0.125f + ((ok1 && gc + 1 <= row_hi) ? 0.0f : -10000.0f);
            mlo = fmaxf(mlo, fmaxf(acc[j][0], acc[j][1]));
            mhi = fmaxf(mhi, fmaxf(acc[j][2], acc[j][3]));
        }
        mlo = fmaxf(mlo, __shfl_xor_sync(0xFFFFFFFFu, mlo, 1));
        mlo = fmaxf(mlo, __shfl_xor_sync(0xFFFFFFFFu, mlo, 2));
        mhi = fmaxf(mhi, __shfl_xor_sync(0xFFFFFFFFu, mhi, 1));
        mhi = fmaxf(mhi, __shfl_xor_sync(0xFFFFFFFFu, mhi, 2));
        if (cf == 0) {
            red[(wm * 16 + r) * 2 + wn]     = mlo;
            red[(wm * 16 + 8 + r) * 2 + wn] = mhi;
        }
        __syncthreads();
        float Mlo = fmaxf(red[(wm * 16 + r) * 2],     red[(wm * 16 + r) * 2 + 1]);
        float Mhi = fmaxf(red[(wm * 16 + 8 + r) * 2], red[(wm * 16 + 8 + r) * 2 + 1]);

        float slo = 0.0f, shi = 0.0f;
        #pragma unroll
        for (int j = 0; j < 16; j++) {
            acc[j][0] = __expf(acc[j][0] - Mlo);
            acc[j][1] = __expf(acc[j][1] - Mlo);
            acc[j][2] = __expf(acc[j][2] - Mhi);
            acc[j][3] = __expf(acc[j][3] - Mhi);
            slo += acc[j][0] + acc[j][1];
            shi += acc[j][2] + acc[j][3];
        }
        slo += __shfl_xor_sync(0xFFFFFFFFu, slo, 1);
        slo += __shfl_xor_sync(0xFFFFFFFFu, slo, 2);
        shi += __shfl_xor_sync(0xFFFFFFFFu, shi, 1);
        shi += __shfl_xor_sync(0xFFFFFFFFu, shi, 2);
        if (cf == 0) {
            red[128 + (wm * 16 + r) * 2 + wn]     = slo;
            red[128 + (wm * 16 + 8 + r) * 2 + wn] = shi;
        }
        __syncthreads();
        float inv_lo = 1.0f / (red[128 + (wm * 16 + r) * 2]     + red[128 + (wm * 16 + r) * 2 + 1]);
        float inv_hi = 1.0f / (red[128 + (wm * 16 + 8 + r) * 2] + red[128 + (wm * 16 + 8 + r) * 2 + 1]);

        #pragma unroll
        for (int j = 0; j < 16; j++) {
            int gc = wn * 128 + j * 8 + cf * 2;
            *(__half2*)(Ph + (wm * 16 + r) * 528 + gc * 2) =
                __floats2half2_rn(acc[j][0] * inv_lo, acc[j][1] * inv_lo);
            *(__half2*)(Ph + (wm * 16 + 8 + r) * 528 + gc * 2) =
                __floats2half2_rn(acc[j][2] * inv_hi, acc[j][3] * inv_hi);
        }
    }
    __syncthreads();

    #pragma unroll
    for (int rp = 0; rp < 4; rp++) {
        int row = (tid >> 2) + rp * 64, c = (tid & 3) * 32;
        const __half* src = Vg + (size_t)row * QKVN + (c >> 1);
        *(float4*)(KV + row * 144 + c)      = *(const float4*)(src);
        *(float4*)(KV + row * 144 + c + 16) = *(const float4*)(src + 8);
    }
    __syncthreads();

    {
        float acc2[4][4];
        #pragma unroll
        for (int j = 0; j < 4; j++)
            #pragma unroll
            for (int p = 0; p < 4; p++) acc2[j][p] = 0.0f;

        const uint32_t poff = sbP + (wm * 16 + ((quad & 1) << 3) + li) * 528
                              + ((quad >> 1) << 4);
        const int vrow_l = ((quad & 1) << 3) + li;
        const int vcol_l = ((quad >> 1) << 3);

        #pragma unroll 4
        for (int ks = 0; ks < 16; ks++) {
            uint32_t pa[4];
            ldsm_x4(pa, poff + ks * 32);
            #pragma unroll
            for (int j2 = 0; j2 < 2; j2++) {
                uint32_t vb[4];
                ldsm_x4_t(vb, sbK + (ks * 16 + vrow_l) * 144
                              + (wn * 32 + j2 * 16 + vcol_l) * 2);
                mma_f16(acc2[2 * j2],     pa, vb);
                mma_f16(acc2[2 * j2 + 1], pa, vb + 2);
            }
        }

        #pragma unroll
        for (int j = 0; j < 4; j++) {
            int lrow = wm * 16 + r;
            int gc   = wn * 32 + j * 8 + cf * 2;
            *(__half2*)(Cg + (size_t)lrow * DD + gc) =
                __floats2half2_rn(acc2[j][0], acc2[j][1]);
            *(__half2*)(Cg + (size_t)(lrow + 8) * DD + gc) =
                __floats2half2_rn(acc2[j][2], acc2[j][3]);
        }
    }
}

// ---------------- host orchestration ----------------
extern "C" void kernel_launch(void* const* d_in, const int* in_sizes, int n_in,
                              void* d_out, int out_size) {
    const int*   ids      = (const int*)  d_in[0];
    const float* item_emb = (const float*)d_in[1];
    const float* pos_emb  = (const float*)d_in[2];
    const float* Wq = (const float*)d_in[3];
    const float* bq = (const float*)d_in[4];
    const float* Wk = (const float*)d_in[5];
    const float* bk = (const float*)d_in[6];
    const float* Wv = (const float*)d_in[7];
    const float* bv = (const float*)d_in[8];
    const float* Wo = (const float*)d_in[9];
    const float* bo = (const float*)d_in[10];
    const float* W1 = (const float*)d_in[11];
    const float* b1 = (const float*)d_in[12];
    const float* W2 = (const float*)d_in[13];
    const float* b2 = (const float*)d_in[14];
    float* out = (float*)d_out;

    float *x, *bqkv;
    __half *xt, *qkv, *ctxt, *ht, *midt, *wt;
    cudaGetSymbolAddress((void**)&x,    g_x);
    cudaGetSymbolAddress((void**)&xt,   g_xt);
    cudaGetSymbolAddress((void**)&qkv,  g_qkv);
    cudaGetSymbolAddress((void**)&ctxt, g_ctxt);
    cudaGetSymbolAddress((void**)&ht,   g_ht);
    cudaGetSymbolAddress((void**)&midt, g_midt);
    cudaGetSymbolAddress((void**)&wt,   g_wt);
    cudaGetSymbolAddress((void**)&bqkv, g_bqkv);

    cudaFuncSetAttribute(attn_fused, cudaFuncAttributeMaxDynamicSharedMemorySize,
                         ATTN_SMEM_BYTES);
    cudaFuncSetAttribute(hgemm<0>, cudaFuncAttributeMaxDynamicSharedMemorySize, HGEMM_SMEM);
    cudaFuncSetAttribute(hgemm<1>, cudaFuncAttributeMaxDynamicSharedMemorySize, HGEMM_SMEM);
    cudaFuncSetAttribute(hgemm_ln<1>, cudaFuncAttributeMaxDynamicSharedMemorySize, HGEMM_LN_SMEM);
    cudaFuncSetAttribute(hgemm_ln<2>, cudaFuncAttributeMaxDynamicSharedMemorySize, HGEMM_LN_SMEM);

    // ---- prologue: weights + biases + embedding ----
    conv_all<<<(LL * 786432 + 255) / 256, 256>>>(Wq, Wk, Wv, Wo, W1, W2, wt);
    {
        dim3 g(3, LL);
        concat_bias<<<g, 256>>>(bq, bk, bv, bqkv);
    }
    embed_ln_kernel<<<MM, 256>>>(ids, item_emb, pos_emb, x, xt, out);

    dim3 gQKV(QKVN / 128, MM / 128);    // (6, 512)
    dim3 gFF1(FF / 128, MM / 128);      // (8, 512)
    dim3 gAttn(SS / 64, BB * HH);       // (4, 1024)

    for (int l = 0; l < LL; l++) {
        __half* base = wt + (size_t)l * 786432;
        const __half* Wqkvt = base;
        const __half* Wot   = base + 196608;
        const __half* W1t   = base + 262144;
        const __half* W2t   = base + 524288;

        hgemm<0><<<gQKV, 256, HGEMM_SMEM>>>(xt, Wqkvt, bqkv + l * QKVN, qkv, DD, QKVN);

        attn_fused<<<gAttn, 256, ATTN_SMEM_BYTES>>>(qkv, ids, ctxt);

        hgemm_ln<1><<<MM / 128, 512, HGEMM_LN_SMEM>>>(
            ctxt, Wot, bo + l * DD, x, ht, nullptr, nullptr, nullptr, DD);

        hgemm<1><<<gFF1, 256, HGEMM_SMEM>>>(ht, W1t, b1 + l * FF, midt, DD, FF);

        hgemm_ln<2><<<MM / 128, 512, HGEMM_LN_SMEM>>>(
            midt, W2t, b2 + l * DD, nullptr, nullptr, x, xt, out, FF);
    }
}

// round 10
// speedup vs baseline: 5.3512x; 1.0593x over previous
#include <cuda_runtime.h>
#include <cuda_fp16.h>
#include <math.h>
#include <stdint.h>

#define BB 256
#define SS 256
#define DD 256
#define HH 4
#define DHH 64
#define LL 2
#define MM (BB*SS)          // 65536
#define FF (4*DD)           // 1024
#define QKVN 768

// ---------------- scratch (no malloc allowed) ----------------
__device__ float g_x  [ (size_t)MM*DD ];                     // fp32 residual
__device__ __align__(16) __half g_xt  [ (size_t)MM*DD ];     // half activations
__device__ __align__(16) __half g_qkv [ (size_t)MM*QKVN ];   // packed q|k|v
__device__ __align__(16) __half g_ctxt[ (size_t)MM*DD ];
__device__ __align__(16) __half g_ht  [ (size_t)MM*DD ];
__device__ __align__(16) __half g_midt[ (size_t)MM*FF ];
__device__ __align__(16) __half g_wt  [ (size_t)LL*786432 ]; // converted weights
__device__ float g_bqkv [ (size_t)LL*QKVN ];                 // concat qkv bias

// ---------------- helpers ----------------
__device__ __forceinline__ float block_sum_256(float v, float* sh) {
    int tid = threadIdx.x;
    sh[tid] = v; __syncthreads();
    #pragma unroll
    for (int s = 128; s > 0; s >>= 1) {
        if (tid < s) sh[tid] += sh[tid + s];
        __syncthreads();
    }
    float r = sh[0];
    __syncthreads();
    return r;
}

__device__ __forceinline__ void mma_f16(float* d, const uint32_t* a, const uint32_t* b) {
    asm volatile("mma.sync.aligned.m16n8k16.row.col.f32.f16.f16.f32 "
        "{%0,%1,%2,%3}, {%4,%5,%6,%7}, {%8,%9}, {%0,%1,%2,%3};"
        : "+f"(d[0]), "+f"(d[1]), "+f"(d[2]), "+f"(d[3])
        : "r"(a[0]), "r"(a[1]), "r"(a[2]), "r"(a[3]), "r"(b[0]), "r"(b[1]));
}

__device__ __forceinline__ void ldsm_x4(uint32_t* d, uint32_t a) {
    asm volatile("ldmatrix.sync.aligned.m8n8.x4.shared.b16 {%0,%1,%2,%3}, [%4];"
        : "=r"(d[0]), "=r"(d[1]), "=r"(d[2]), "=r"(d[3]) : "r"(a));
}
__device__ __forceinline__ void ldsm_x4_t(uint32_t* d, uint32_t a) {
    asm volatile("ldmatrix.sync.aligned.m8n8.x4.trans.shared.b16 {%0,%1,%2,%3}, [%4];"
        : "=r"(d[0]), "=r"(d[1]), "=r"(d[2]), "=r"(d[3]) : "r"(a));
}

__device__ __forceinline__ void cp_async16(uint32_t s, const void* g) {
    asm volatile("cp.async.cg.shared.global [%0], [%1], 16;" :: "r"(s), "l"(g));
}
__device__ __forceinline__ void cp_commit() { asm volatile("cp.async.commit_group;"); }
template<int N_> __device__ __forceinline__ void cp_wait() {
    asm volatile("cp.async.wait_group %0;" :: "n"(N_));
}

__device__ __forceinline__ uint32_t smem_u32(const void* p) {
    uint32_t a;
    asm("{ .reg .u64 t; cvta.to.shared.u64 t, %1; cvt.u32.u64 %0, t; }" : "=r"(a) : "l"(p));
    return a;
}

// ---------------- batched weight convert (all layers, one launch) ----------------
__global__ void conv_all(const float* __restrict__ Wq, const float* __restrict__ Wk,
                         const float* __restrict__ Wv, const float* __restrict__ Wo,
                         const float* __restrict__ W1, const float* __restrict__ W2,
                         __half* __restrict__ wt) {
    size_t idx = (size_t)blockIdx.x * 256 + threadIdx.x;
    if (idx >= (size_t)LL * 786432) return;
    int l = (int)(idx / 786432);
    int off = (int)(idx % 786432);
    const float* src; int N, K, local;
    if (off < 196608) {
        int w = off >> 16; local = off & 65535; K = 256; N = 256;
        src = (w == 0 ? Wq : (w == 1 ? Wk : Wv)) + (size_t)l * 65536;
    } else if (off < 262144) {
        local = off - 196608; K = 256; N = 256; src = Wo + (size_t)l * 65536;
    } else if (off < 524288) {
        local = off - 262144; K = 256; N = 1024; src = W1 + (size_t)l * 262144;
    } else {
        local = off - 524288; K = 1024; N = 256; src = W2 + (size_t)l * 262144;
    }
    int n = local / K, k = local % K;
    wt[idx] = __float2half_rn(src[(size_t)k * N + n]);
}

__global__ void concat_bias(const float* __restrict__ bq, const float* __restrict__ bk,
                            const float* __restrict__ bv, float* __restrict__ dst) {
    int l = blockIdx.y;
    int i = blockIdx.x * 256 + threadIdx.x;
    float v = (i < 256) ? bq[l * 256 + i]
            : (i < 512) ? bk[l * 256 + i - 256]
                        : bv[l * 256 + i - 512];
    dst[l * QKVN + i] = v;
}

// ---------------- embedding + LN ----------------
__global__ void embed_ln_kernel(const int* __restrict__ ids,
                                const float* __restrict__ item_emb,
                                const float* __restrict__ pos_emb,
                                float* __restrict__ x, __half* __restrict__ xt,
                                float* __restrict__ out) {
    __shared__ float sh[256];
    int row = blockIdx.x;
    int s   = row & (SS - 1);
    int tid = threadIdx.x;
    int id  = ids[row];
    float v = item_emb[(size_t)id * DD + tid] + pos_emb[s * DD + tid];
    float mu  = block_sum_256(v, sh) * (1.0f / DD);
    float d   = v - mu;
    float var = block_sum_256(d * d, sh) * (1.0f / DD);
    float o   = d * rsqrtf(var + 1e-5f);
    size_t idx = (size_t)row * DD + tid;
    x[idx] = o;
    out[idx] = o;
    xt[idx] = __float2half_rn(o);
}

// =====================================================================
// FP16 GEMM: 128x128 tile, BK=64, 3-stage cp.async, 8 warps.
// Rows stored as 128B data + 16B pad (144B stride -> conflict-free ldsm).
// =====================================================================
#define HGEMM_SMEM (3 * 36864)

template<int GELU>
__global__ void __launch_bounds__(256, 2)
hgemm(const __half* __restrict__ A, const __half* __restrict__ Bt,
      const float* __restrict__ bias, __half* __restrict__ C, int K, int N)
{
    extern __shared__ char smem[];
    const uint32_t sb = smem_u32(smem);

    const int tid  = threadIdx.x;
    const int lane = tid & 31;
    const int wid  = tid >> 5;
    const int warp_m = wid & 1;
    const int warp_n = wid >> 1;
    const int r  = lane >> 2;
    const int cf = lane & 3;
    const int quad = lane >> 3, li = lane & 7;

    const int bm = blockIdx.y << 7;
    const int bn = blockIdx.x << 7;

    // loader: thread covers row tid>>1, 64B half (tid&1) of the 128B row
    const int lrow = tid >> 1;
    const int lcb  = (tid & 1) * 64;                 // byte offset in row
    const __half* Ag = A  + (size_t)(bm + lrow) * K + (lcb >> 1);
    const __half* Bg = Bt + (size_t)(bn + lrow) * K + (lcb >> 1);
    const uint32_t sA = sb +         lrow * 144 + lcb;
    const uint32_t sB = sb + 18432 + lrow * 144 + lcb;

    const int nsteps = K >> 6;

    #pragma unroll
    for (int s = 0; s < 2; s++) {
        const uint32_t o = s * 36864;
        #pragma unroll
        for (int g = 0; g < 4; g++) {
            cp_async16(sA + o + g * 16, Ag + s * 64 + g * 8);
            cp_async16(sB + o + g * 16, Bg + s * 64 + g * 8);
        }
        cp_commit();
    }

    const uint32_t aoff = (uint32_t)((warp_m * 64 + ((quad & 1) << 3) + li) * 144
                                     + ((quad >> 1) << 4));
    const uint32_t boff = (uint32_t)(18432 + (warp_n * 32 + ((quad & 2) ? 8 : 0) + li) * 144
                                     + ((quad & 1) << 4));

    float acc[4][4][4];
    #pragma unroll
    for (int i = 0; i < 4; i++)
        #pragma unroll
        for (int j = 0; j < 4; j++)
            #pragma unroll
            for (int p = 0; p < 4; p++) acc[i][j][p] = 0.0f;

    for (int s = 0; s < nsteps; s++) {
        if (s + 1 < nsteps) cp_wait<1>(); else cp_wait<0>();
        __syncthreads();
        if (s + 2 < nsteps) {
            const uint32_t o = ((s + 2) % 3) * 36864;
            #pragma unroll
            for (int g = 0; g < 4; g++) {
                cp_async16(sA + o + g * 16, Ag + (s + 2) * 64 + g * 8);
                cp_async16(sB + o + g * 16, Bg + (s + 2) * 64 + g * 8);
            }
            cp_commit();
        }
        const uint32_t stg = sb + (s % 3) * 36864;

        #pragma unroll
        for (int ks = 0; ks < 4; ks++) {
            uint32_t af[4][4];
            #pragma unroll
            for (int i = 0; i < 4; i++)
                ldsm_x4(af[i], stg + aoff + i * 2304 + ks * 32);
            #pragma unroll
            for (int j2 = 0; j2 < 2; j2++) {
                uint32_t bf[4];
                ldsm_x4(bf, stg + boff + j2 * 2304 + ks * 32);
                #pragma unroll
                for (int i = 0; i < 4; i++) {
                    mma_f16(acc[i][2 * j2],     af[i], bf);
                    mma_f16(acc[i][2 * j2 + 1], af[i], bf + 2);
                }
            }
        }
    }

    #pragma unroll
    for (int i = 0; i < 4; i++) {
        #pragma unroll
        for (int j = 0; j < 4; j++) {
            int gr0 = bm + warp_m * 64 + i * 16 + r;
            int gc  = bn + warp_n * 32 + j * 8 + cf * 2;
            float v00 = acc[i][j][0] + bias[gc];
            float v01 = acc[i][j][1] + bias[gc + 1];
            float v10 = acc[i][j][2] + bias[gc];
            float v11 = acc[i][j][3] + bias[gc + 1];
            if (GELU) {
                v00 = 0.5f * v00 * (1.0f + erff(v00 * 0.7071067811865476f));
                v01 = 0.5f * v01 * (1.0f + erff(v01 * 0.7071067811865476f));
                v10 = 0.5f * v10 * (1.0f + erff(v10 * 0.7071067811865476f));
                v11 = 0.5f * v11 * (1.0f + erff(v11 * 0.7071067811865476f));
            }
            *(__half2*)(C + (size_t)gr0 * N + gc)       = __floats2half2_rn(v00, v01);
            *(__half2*)(C + (size_t)(gr0 + 8) * N + gc) = __floats2half2_rn(v10, v11);
        }
    }
}

// =====================================================================
// FP16 GEMM + fused LayerNorm epilogue. Tile 128x256, BK=64, 512 thr.
// MODE 1 (Wo):  ht = LN(A@W + bias + resid) -> Ch (half)
// MODE 2 (FF2): o = LN(A@W + bias); x=o; total+=o; xt=half(o)
// =====================================================================
#define HGEMM_LN_SMEM (3 * 55296)

template<int MODE>
__global__ void __launch_bounds__(512, 1)
hgemm_ln(const __half* __restrict__ A, const __half* __restrict__ Bt,
         const float* __restrict__ bias, const float* __restrict__ resid,
         __half* __restrict__ Ch, float* __restrict__ x,
         __half* __restrict__ xt, float* __restrict__ total, int K)
{
    extern __shared__ char smem[];
    const uint32_t sb = smem_u32(smem);
    const int N = 256;

    const int tid  = threadIdx.x;
    const int lane = tid & 31;
    const int wid  = tid >> 5;
    const int warp_m = wid & 1;
    const int warp_n = wid >> 1;           // 0..7
    const int r  = lane >> 2;
    const int cf = lane & 3;
    const int quad = lane >> 3, li = lane & 7;

    const int bm = blockIdx.x << 7;

    // A: 128 rows x 8 16B-chunks = 1024 -> 2/thread; B: 256 rows -> 4/thread
    const int ar0 = tid >> 3,           ac0 = (tid & 7) * 16;
    const int ar1 = (tid + 512) >> 3,   ac1 = ac0;
    const __half* Ag0 = A + (size_t)(bm + ar0) * K + (ac0 >> 1);
    const __half* Ag1 = A + (size_t)(bm + ar1) * K + (ac1 >> 1);
    const uint32_t sA0 = sb + ar0 * 144 + ac0;
    const uint32_t sA1 = sb + ar1 * 144 + ac1;

    const int nsteps = K >> 6;

    #pragma unroll
    for (int s = 0; s < 2; s++) {
        const uint32_t o = s * 55296;
        cp_async16(sA0 + o, Ag0 + s * 64);
        cp_async16(sA1 + o, Ag1 + s * 64);
        #pragma unroll
        for (int i = 0; i < 4; i++) {
            int c = tid + i * 512;
            int br = c >> 3, bc = (c & 7) * 16;
            cp_async16(sb + 18432 + br * 144 + bc + o,
                       Bt + (size_t)br * K + s * 64 + (bc >> 1));
        }
        cp_commit();
    }

    const uint32_t aoff = (uint32_t)((warp_m * 64 + ((quad & 1) << 3) + li) * 144
                                     + ((quad >> 1) << 4));
    const uint32_t boff = (uint32_t)(18432 + (warp_n * 32 + ((quad & 2) ? 8 : 0) + li) * 144
                                     + ((quad & 1) << 4));

    float acc[4][4][4];
    #pragma unroll
    for (int i = 0; i < 4; i++)
        #pragma unroll
        for (int j = 0; j < 4; j++)
            #pragma unroll
            for (int p = 0; p < 4; p++) acc[i][j][p] = 0.0f;

    for (int s = 0; s < nsteps; s++) {
        if (s + 1 < nsteps) cp_wait<1>(); else cp_wait<0>();
        __syncthreads();
        if (s + 2 < nsteps) {
            const uint32_t o = ((s + 2) % 3) * 55296;
            cp_async16(sA0 + o, Ag0 + (s + 2) * 64);
            cp_async16(sA1 + o, Ag1 + (s + 2) * 64);
            #pragma unroll
            for (int i = 0; i < 4; i++) {
                int c = tid + i * 512;
                int br = c >> 3, bc = (c & 7) * 16;
                cp_async16(sb + 18432 + br * 144 + bc + o,
                           Bt + (size_t)br * K + (s + 2) * 64 + (bc >> 1));
            }
            cp_commit();
        }
        const uint32_t stg = sb + (s % 3) * 55296;

        #pragma unroll
        for (int ks = 0; ks < 4; ks++) {
            uint32_t af[4][4];
            #pragma unroll
            for (int i = 0; i < 4; i++)
                ldsm_x4(af[i], stg + aoff + i * 2304 + ks * 32);
            #pragma unroll
            for (int j2 = 0; j2 < 2; j2++) {
                uint32_t bf[4];
                ldsm_x4(bf, stg + boff + j2 * 2304 + ks * 32);
                #pragma unroll
                for (int i = 0; i < 4; i++) {
                    mma_f16(acc[i][2 * j2],     af[i], bf);
                    mma_f16(acc[i][2 * j2 + 1], af[i], bf + 2);
                }
            }
        }
    }
    __syncthreads();   // smem free -> LN buffers

    // ---- bias (+resid) ----
    #pragma unroll
    for (int i = 0; i < 4; i++) {
        int gr0 = bm + warp_m * 64 + i * 16 + r;
        #pragma unroll
        for (int j = 0; j < 4; j++) {
            int gc = warp_n * 32 + j * 8 + cf * 2;
            float b0 = bias[gc], b1 = bias[gc + 1];
            acc[i][j][0] += b0; acc[i][j][1] += b1;
            acc[i][j][2] += b0; acc[i][j][3] += b1;
            if (MODE == 1) {
                acc[i][j][0] += resid[(size_t)gr0 * N + gc];
                acc[i][j][1] += resid[(size_t)gr0 * N + gc + 1];
                acc[i][j][2] += resid[(size_t)(gr0 + 8) * N + gc];
                acc[i][j][3] += resid[(size_t)(gr0 + 8) * N + gc + 1];
            }
        }
    }

    // ---- LN pass 1: mean ----
    float* redA = (float*)smem;
    float* redB = (float*)(smem + 4096);
    #pragma unroll
    for (int i = 0; i < 4; i++) {
        float s_lo = 0.0f, s_hi = 0.0f;
        #pragma unroll
        for (int j = 0; j < 4; j++) {
            s_lo += acc[i][j][0] + acc[i][j][1];
            s_hi += acc[i][j][2] + acc[i][j][3];
        }
        s_lo += __shfl_xor_sync(0xFFFFFFFFu, s_lo, 1);
        s_lo += __shfl_xor_sync(0xFFFFFFFFu, s_lo, 2);
        s_hi += __shfl_xor_sync(0xFFFFFFFFu, s_hi, 1);
        s_hi += __shfl_xor_sync(0xFFFFFFFFu, s_hi, 2);
        if (cf == 0) {
            int rl = warp_m * 64 + i * 16 + r;
            redA[rl * 8 + warp_n]       = s_lo;
            redA[(rl + 8) * 8 + warp_n] = s_hi;
        }
    }
    __syncthreads();
    float mu[4][2];
    #pragma unroll
    for (int i = 0; i < 4; i++) {
        int rl = warp_m * 64 + i * 16 + r;
        float a = 0.0f, b = 0.0f;
        #pragma unroll
        for (int w = 0; w < 8; w++) { a += redA[rl * 8 + w]; b += redA[(rl + 8) * 8 + w]; }
        mu[i][0] = a * (1.0f / 256.0f);
        mu[i][1] = b * (1.0f / 256.0f);
    }

    // ---- LN pass 2: variance ----
    #pragma unroll
    for (int i = 0; i < 4; i++) {
        float s_lo = 0.0f, s_hi = 0.0f;
        #pragma unroll
        for (int j = 0; j < 4; j++) {
            float d0 = acc[i][j][0] - mu[i][0], d1 = acc[i][j][1] - mu[i][0];
            float d2 = acc[i][j][2] - mu[i][1], d3 = acc[i][j][3] - mu[i][1];
            s_lo += d0 * d0 + d1 * d1;
            s_hi += d2 * d2 + d3 * d3;
        }
        s_lo += __shfl_xor_sync(0xFFFFFFFFu, s_lo, 1);
        s_lo += __shfl_xor_sync(0xFFFFFFFFu, s_lo, 2);
        s_hi += __shfl_xor_sync(0xFFFFFFFFu, s_hi, 1);
        s_hi += __shfl_xor_sync(0xFFFFFFFFu, s_hi, 2);
        if (cf == 0) {
            int rl = warp_m * 64 + i * 16 + r;
            redB[rl * 8 + warp_n]       = s_lo;
            redB[(rl + 8) * 8 + warp_n] = s_hi;
        }
    }
    __syncthreads();

    #pragma unroll
    for (int i = 0; i < 4; i++) {
        int rl = warp_m * 64 + i * 16 + r;
        float a = 0.0f, b = 0.0f;
        #pragma unroll
        for (int w = 0; w < 8; w++) { a += redB[rl * 8 + w]; b += redB[(rl + 8) * 8 + w]; }
        float rs_lo = rsqrtf(a * (1.0f / 256.0f) + 1e-5f);
        float rs_hi = rsqrtf(b * (1.0f / 256.0f) + 1e-5f);
        int gr0 = bm + rl;
        #pragma unroll
        for (int j = 0; j < 4; j++) {
            int gc = warp_n * 32 + j * 8 + cf * 2;
            float o00 = (acc[i][j][0] - mu[i][0]) * rs_lo;
            float o01 = (acc[i][j][1] - mu[i][0]) * rs_lo;
            float o10 = (acc[i][j][2] - mu[i][1]) * rs_hi;
            float o11 = (acc[i][j][3] - mu[i][1]) * rs_hi;
            if (MODE == 1) {
                *(__half2*)(Ch + (size_t)gr0 * N + gc)       = __floats2half2_rn(o00, o01);
                *(__half2*)(Ch + (size_t)(gr0 + 8) * N + gc) = __floats2half2_rn(o10, o11);
            } else {
                size_t i0 = (size_t)gr0 * N + gc;
                size_t i1 = (size_t)(gr0 + 8) * N + gc;
                *(float2*)(x + i0) = make_float2(o00, o01);
                *(float2*)(x + i1) = make_float2(o10, o11);
                float2 t0 = *(float2*)(total + i0);
                float2 t1 = *(float2*)(total + i1);
                t0.x += o00; t0.y += o01; t1.x += o10; t1.y += o11;
                *(float2*)(total + i0) = t0;
                *(float2*)(total + i1) = t1;
                *(__half2*)(xt + i0) = __floats2half2_rn(o00, o01);
                *(__half2*)(xt + i1) = __floats2half2_rn(o10, o11);
            }
        }
    }
}

// =====================================================================
// Fused FP16 attention (packed qkv). V is cp.async-prefetched during softmax.
// =====================================================================
#define ATTN_SMEM_BYTES 81920

__global__ void __launch_bounds__(256, 2)
attn_fused(const __half* __restrict__ qkv, const int* __restrict__ ids,
           __half* __restrict__ ctxt)
{
    extern __shared__ char sm[];
    char* Qs = sm;                    // 9216 B
    char* KV = sm + 9216;             // 36864 B
    char* Ph = sm + 46080;            // 33792 B
    float* red   = (float*)(sm + 79872);
    int*   ids_s = (int*)(sm + 80896);

    const int tid  = threadIdx.x;
    const int lane = tid & 31;
    const int wid  = tid >> 5;
    const int r  = lane >> 2;
    const int cf = lane & 3;
    const int quad = lane >> 3, li = lane & 7;

    const int qb = blockIdx.x;
    const int bh = blockIdx.y;
    const int b  = bh >> 2, h = bh & 3;

    const __half* Qg = qkv + ((size_t)b * SS + qb * 64) * QKVN + h * DHH;
    const __half* Kg = qkv + (size_t)b * SS * QKVN + 256 + h * DHH;
    const __half* Vg = qkv + (size_t)b * SS * QKVN + 512 + h * DHH;
    __half* Cg = ctxt + (size_t)b * SS * DD + h * DHH + (size_t)qb * 64 * DD;
    const int* idb = ids + b * SS;

    ids_s[tid] = idb[tid];

    {
        int row = tid >> 2, c = (tid & 3) * 32;
        const __half* src = Qg + (size_t)row * QKVN + (c >> 1);
        *(float4*)(Qs + row * 144 + c)      = *(const float4*)(src);
        *(float4*)(Qs + row * 144 + c + 16) = *(const float4*)(src + 8);
    }
    #pragma unroll
    for (int rp = 0; rp < 4; rp++) {
        int row = (tid >> 2) + rp * 64, c = (tid & 3) * 32;
        const __half* src = Kg + (size_t)row * QKVN + (c >> 1);
        *(float4*)(KV + row * 144 + c)      = *(const float4*)(src);
        *(float4*)(KV + row * 144 + c + 16) = *(const float4*)(src + 8);
    }
    __syncthreads();

    const int wm = wid & 3, wn = wid >> 2;
    const uint32_t sbQ = smem_u32(Qs);
    const uint32_t sbK = smem_u32(KV);
    const uint32_t sbP = smem_u32(Ph);

    float acc[16][4];
    #pragma unroll
    for (int j = 0; j < 16; j++)
        #pragma unroll
        for (int p = 0; p < 4; p++) acc[j][p] = 0.0f;

    {
        uint32_t qa[4][4];
        const uint32_t qoff = sbQ + (wm * 16 + ((quad & 1) << 3) + li) * 144
                              + ((quad >> 1) << 4);
        #pragma unroll
        for (int ks = 0; ks < 4; ks++) ldsm_x4(qa[ks], qoff + ks * 32);

        const uint32_t koff = sbK + (((quad & 2) ? 8 : 0) + li) * 144 + ((quad & 1) << 4);
        #pragma unroll
        for (int j2 = 0; j2 < 8; j2++) {
            #pragma unroll
            for (int ks = 0; ks < 4; ks++) {
                uint32_t bf[4];
                ldsm_x4(bf, koff + (wn * 128 + j2 * 16) * 144 + ks * 32);
                mma_f16(acc[2 * j2],     qa[ks], bf);
                mma_f16(acc[2 * j2 + 1], qa[ks], bf + 2);
            }
        }
    }

    {
        const int row_lo = qb * 64 + wm * 16 + r;
        const int row_hi = row_lo + 8;
        float mlo = -1e30f, mhi = -1e30f;
        #pragma unroll
        for (int j = 0; j < 16; j++) {
            int gc = wn * 128 + j * 8 + cf * 2;
            bool ok0 = ids_s[gc] > 0, ok1 = ids_s[gc + 1] > 0;
            acc[j][0] = acc[j][0] * 0.125f + ((ok0 && gc     <= row_lo) ? 0.0f : -10000.0f);
            acc[j][1] = acc[j][1] * 0.125f + ((ok1 && gc + 1 <= row_lo) ? 0.0f : -10000.0f);
            acc[j][2] = acc[j][2] * 0.125f + ((ok0 && gc     <= row_hi) ? 0.0f : -10000.0f);
            acc[j][3] = acc[j][3] * 0.125f + ((ok1 && gc + 1 <= row_hi) ? 0.0f : -10000.0f);
            mlo = fmaxf(mlo, fmaxf(acc[j][0], acc[j][1]));
            mhi = fmaxf(mhi, fmaxf(acc[j][2], acc[j][3]));
        }
        mlo = fmaxf(mlo, __shfl_xor_sync(0xFFFFFFFFu, mlo, 1));
        mlo = fmaxf(mlo, __shfl_xor_sync(0xFFFFFFFFu, mlo, 2));
        mhi = fmaxf(mhi, __shfl_xor_sync(0xFFFFFFFFu, mhi, 1));
        mhi = fmaxf(mhi, __shfl_xor_sync(0xFFFFFFFFu, mhi, 2));
        if (cf == 0) {
            red[(wm * 16 + r) * 2 + wn]     = mlo;
            red[(wm * 16 + 8 + r) * 2 + wn] = mhi;
        }
        __syncthreads();   // all score MMAs done -> K buffer is dead

        // ---- prefetch V into KV (overlaps exp/sum below) ----
        {
            int row0 = tid >> 2, c = (tid & 3) * 32;
            #pragma unroll
            for (int rp = 0; rp < 4; rp++) {
                int row = row0 + rp * 64;
                const __half* src = Vg + (size_t)row * QKVN + (c >> 1);
                cp_async16(sbK + row * 144 + c,      src);
                cp_async16(sbK + row * 144 + c + 16, src + 8);
            }
            cp_commit();
        }

        float Mlo = fmaxf(red[(wm * 16 + r) * 2],     red[(wm * 16 + r) * 2 + 1]);
        float Mhi = fmaxf(red[(wm * 16 + 8 + r) * 2], red[(wm * 16 + 8 + r) * 2 + 1]);

        float slo = 0.0f, shi = 0.0f;
        #pragma unroll
        for (int j = 0; j < 16; j++) {
            acc[j][0] = __expf(acc[j][0] - Mlo);
            acc[j][1] = __expf(acc[j][1] - Mlo);
            acc[j][2] = __expf(acc[j][2] - Mhi);
            acc[j][3] = __expf(acc[j][3] - Mhi);
            slo += acc[j][0] + acc[j][1];
            shi += acc[j][2] + acc[j][3];
        }
        slo += __shfl_xor_sync(0xFFFFFFFFu, slo, 1);
        slo += __shfl_xor_sync(0xFFFFFFFFu, slo, 2);
        shi += __shfl_xor_sync(0xFFFFFFFFu, shi, 1);
        shi += __shfl_xor_sync(0xFFFFFFFFu, shi, 2);
        if (cf == 0) {
            red[128 + (wm * 16 + r) * 2 + wn]     = slo;
            red[128 + (wm * 16 + 8 + r) * 2 + wn] = shi;
        }
        __syncthreads();
        float inv_lo = 1.0f / (red[128 + (wm * 16 + r) * 2]     + red[128 + (wm * 16 + r) * 2 + 1]);
        float inv_hi = 1.0f / (red[128 + (wm * 16 + 8 + r) * 2] + red[128 + (wm * 16 + 8 + r) * 2 + 1]);

        #pragma unroll
        for (int j = 0; j < 16; j++) {
            int gc = wn * 128 + j * 8 + cf * 2;
            *(__half2*)(Ph + (wm * 16 + r) * 528 + gc * 2) =
                __floats2half2_rn(acc[j][0] * inv_lo, acc[j][1] * inv_lo);
            *(__half2*)(Ph + (wm * 16 + 8 + r) * 528 + gc * 2) =
                __floats2half2_rn(acc[j][2] * inv_hi, acc[j][3] * inv_hi);
        }
    }
    cp_wait<0>();
    __syncthreads();   // Ph visible + V arrived

    {
        float acc2[4][4];
        #pragma unroll
        for (int j = 0; j < 4; j++)
            #pragma unroll
            for (int p = 0; p < 4; p++) acc2[j][p] = 0.0f;

        const uint32_t poff = sbP + (wm * 16 + ((quad & 1) << 3) + li) * 528
                              + ((quad >> 1) << 4);
        const int vrow_l = ((quad & 1) << 3) + li;
        const int vcol_l = ((quad >> 1) << 3);

        #pragma unroll 4
        for (int ks = 0; ks < 16; ks++) {
            uint32_t pa[4];
            ldsm_x4(pa, poff + ks * 32);
            #pragma unroll
            for (int j2 = 0; j2 < 2; j2++) {
                uint32_t vb[4];
                ldsm_x4_t(vb, sbK + (ks * 16 + vrow_l) * 144
                              + (wn * 32 + j2 * 16 + vcol_l) * 2);
                mma_f16(acc2[2 * j2],     pa, vb);
                mma_f16(acc2[2 * j2 + 1], pa, vb + 2);
            }
        }

        #pragma unroll
        for (int j = 0; j < 4; j++) {
            int lrow = wm * 16 + r;
            int gc   = wn * 32 + j * 8 + cf * 2;
            *(__half2*)(Cg + (size_t)lrow * DD + gc) =
                __floats2half2_rn(acc2[j][0], acc2[j][1]);
            *(__half2*)(Cg + (size_t)(lrow + 8) * DD + gc) =
                __floats2half2_rn(acc2[j][2], acc2[j][3]);
        }
    }
}

// ---------------- host orchestration ----------------
extern "C" void kernel_launch(void* const* d_in, const int* in_sizes, int n_in,
                              void* d_out, int out_size) {
    const int*   ids      = (const int*)  d_in[0];
    const float* item_emb = (const float*)d_in[1];
    const float* pos_emb  = (const float*)d_in[2];
    const float* Wq = (const float*)d_in[3];
    const float* bq = (const float*)d_in[4];
    const float* Wk = (const float*)d_in[5];
    const float* bk = (const float*)d_in[6];
    const float* Wv = (const float*)d_in[7];
    const float* bv = (const float*)d_in[8];
    const float* Wo = (const float*)d_in[9];
    const float* bo = (const float*)d_in[10];
    const float* W1 = (const float*)d_in[11];
    const float* b1 = (const float*)d_in[12];
    const float* W2 = (const float*)d_in[13];
    const float* b2 = (const float*)d_in[14];
    float* out = (float*)d_out;

    float *x, *bqkv;
    __half *xt, *qkv, *ctxt, *ht, *midt, *wt;
    cudaGetSymbolAddress((void**)&x,    g_x);
    cudaGetSymbolAddress((void**)&xt,   g_xt);
    cudaGetSymbolAddress((void**)&qkv,  g_qkv);
    cudaGetSymbolAddress((void**)&ctxt, g_ctxt);
    cudaGetSymbolAddress((void**)&ht,   g_ht);
    cudaGetSymbolAddress((void**)&midt, g_midt);
    cudaGetSymbolAddress((void**)&wt,   g_wt);
    cudaGetSymbolAddress((void**)&bqkv, g_bqkv);

    cudaFuncSetAttribute(attn_fused, cudaFuncAttributeMaxDynamicSharedMemorySize,
                         ATTN_SMEM_BYTES);
    cudaFuncSetAttribute(hgemm<0>, cudaFuncAttributeMaxDynamicSharedMemorySize, HGEMM_SMEM);
    cudaFuncSetAttribute(hgemm<1>, cudaFuncAttributeMaxDynamicSharedMemorySize, HGEMM_SMEM);
    cudaFuncSetAttribute(hgemm_ln<1>, cudaFuncAttributeMaxDynamicSharedMemorySize, HGEMM_LN_SMEM);
    cudaFuncSetAttribute(hgemm_ln<2>, cudaFuncAttributeMaxDynamicSharedMemorySize, HGEMM_LN_SMEM);

    conv_all<<<(LL * 786432 + 255) / 256, 256>>>(Wq, Wk, Wv, Wo, W1, W2, wt);
    {
        dim3 g(3, LL);
        concat_bias<<<g, 256>>>(bq, bk, bv, bqkv);
    }
    embed_ln_kernel<<<MM, 256>>>(ids, item_emb, pos_emb, x, xt, out);

    dim3 gQKV(QKVN / 128, MM / 128);    // (6, 512)
    dim3 gFF1(FF / 128, MM / 128);      // (8, 512)
    dim3 gAttn(SS / 64, BB * HH);       // (4, 1024)

    for (int l = 0; l < LL; l++) {
        __half* base = wt + (size_t)l * 786432;
        const __half* Wqkvt = base;
        const __half* Wot   = base + 196608;
        const __half* W1t   = base + 262144;
        const __half* W2t   = base + 524288;

        hgemm<0><<<gQKV, 256, HGEMM_SMEM>>>(xt, Wqkvt, bqkv + l * QKVN, qkv, DD, QKVN);

        attn_fused<<<gAttn, 256, ATTN_SMEM_BYTES>>>(qkv, ids, ctxt);

        hgemm_ln<1><<<MM / 128, 512, HGEMM_LN_SMEM>>>(
            ctxt, Wot, bo + l * DD, x, ht, nullptr, nullptr, nullptr, DD);

        hgemm<1><<<gFF1, 256, HGEMM_SMEM>>>(ht, W1t, b1 + l * FF, midt, DD, FF);

        hgemm_ln<2><<<MM / 128, 512, HGEMM_LN_SMEM>>>(
            midt, W2t, b2 + l * DD, nullptr, nullptr, x, xt, out, FF);
    }
}